// round 9
// baseline (speedup 1.0000x reference)
#include <cuda_runtime.h>
#include <cuda_fp16.h>
#include <math.h>
#include <stdint.h>

// Problem constants
#define Bx   64
#define Nx   1024
#define Cx   768
#define Hx   12
#define DHx  64
#define Kx   64
#define SCALEx 0.125f
#define LN_EPSx 1e-6f

// ------------------------- device scratch -------------------------
__device__ float g_q   [(long long)Bx * Nx * Cx];
__device__ float g_k   [(long long)Bx * Kx * Cx];
__device__ float g_v   [(long long)Bx * Kx * Cx];
__device__ float g_rfk [(long long)Bx * Hx * 32 * DHx];
__device__ float g_beta[(long long)Bx * Hx * 32 * DHx];

// fp16 planes (row-major)
__device__ __half g_qH   [(long long)Bx * Nx * Cx];
__device__ __half g_attH [(long long)Bx * Nx * Cx];
__device__ __half g_kdsH [Kx * Nx];
__device__ __half g_kdsL [Kx * Nx];
__device__ __half g_vdsH [Kx * Nx];
__device__ __half g_vdsL [Kx * Nx];
__device__ __half g_keyTH[(long long)Bx * Cx * Nx];
__device__ __half g_keyTL[(long long)Bx * Cx * Nx];
__device__ __half g_valTH[(long long)Bx * Cx * Nx];
__device__ __half g_valTL[(long long)Bx * Cx * Nx];
__device__ __half g_kdH  [(long long)Bx * Kx * Cx];
__device__ __half g_kdL  [(long long)Bx * Kx * Cx];
__device__ __half g_vdH  [(long long)Bx * Kx * Cx];
__device__ __half g_vdL  [(long long)Bx * Kx * Cx];
__device__ __half g_wqTH [Cx * Cx];
__device__ __half g_wqTL [Cx * Cx];
__device__ __half g_wkTH [Cx * Cx];
__device__ __half g_wkTL [Cx * Cx];
__device__ __half g_wvTH [Cx * Cx];
__device__ __half g_wvTL [Cx * Cx];
__device__ __half g_woTH [Cx * Cx];
__device__ __half g_woTL [Cx * Cx];

// ------------------------- helpers -------------------------
__device__ __forceinline__ uint32_t smem_u32(const void* p) {
    uint32_t a;
    asm("{ .reg .u64 t; cvta.to.shared.u64 t, %1; cvt.u32.u64 %0, t; }" : "=r"(a) : "l"(p));
    return a;
}
__device__ __forceinline__ void cp16(uint32_t dst, const void* src, int srcsz) {
    asm volatile("cp.async.cg.shared.global [%0], [%1], 16, %2;"
                 :: "r"(dst), "l"(src), "r"(srcsz) : "memory");
}
#define CP_COMMIT() asm volatile("cp.async.commit_group;" ::: "memory")
#define CP_WAIT1()  asm volatile("cp.async.wait_group 1;" ::: "memory")
#define CP_WAIT0()  asm volatile("cp.async.wait_group 0;" ::: "memory")

__device__ __forceinline__ void ldm_x4(uint32_t* r, uint32_t a) {
    asm volatile("ldmatrix.sync.aligned.m8n8.x4.shared.b16 {%0,%1,%2,%3}, [%4];"
                 : "=r"(r[0]), "=r"(r[1]), "=r"(r[2]), "=r"(r[3]) : "r"(a));
}
__device__ __forceinline__ void mma_f16(float* d, const uint32_t* a, const uint32_t* b) {
    asm volatile("mma.sync.aligned.m16n8k16.row.col.f32.f16.f16.f32 "
                 "{%0,%1,%2,%3},{%4,%5,%6,%7},{%8,%9},{%0,%1,%2,%3};"
                 : "+f"(d[0]), "+f"(d[1]), "+f"(d[2]), "+f"(d[3])
                 : "r"(a[0]), "r"(a[1]), "r"(a[2]), "r"(a[3]), "r"(b[0]), "r"(b[1]));
}

// ------------------------- convert (row-major, hi [+lo]) -------------------------
__global__ __launch_bounds__(256)
void convert16(const float* __restrict__ in,
               __half* __restrict__ oh, __half* __restrict__ ol,
               long long total4)
{
    const long long g = (long long)blockIdx.x * 256 + threadIdx.x;
    if (g >= total4) return;
    float4 f = ((const float4*)in)[g];
    __half h[4];
    h[0] = __float2half(f.x); h[1] = __float2half(f.y);
    h[2] = __float2half(f.z); h[3] = __float2half(f.w);
    *(uint2*)(oh + g * 4) = *(uint2*)h;
    if (ol) {
        __half l[4];
        l[0] = __float2half(f.x - __half2float(h[0]));
        l[1] = __float2half(f.y - __half2float(h[1]));
        l[2] = __float2half(f.z - __half2float(h[2]));
        l[3] = __float2half(f.w - __half2float(h[3]));
        *(uint2*)(ol + g * 4) = *(uint2*)l;
    }
}

// ------------------------- transpose + split ------------
__global__ __launch_bounds__(256)
void transpose_split16(const float* __restrict__ in,
                       __half* __restrict__ oh, __half* __restrict__ ol,
                       int R, int Cc, long long sIn, long long sOut)
{
    __shared__ float t[64][65];
    in += (long long)blockIdx.z * sIn;
    oh += (long long)blockIdx.z * sOut;
    ol += (long long)blockIdx.z * sOut;
    const int r0 = blockIdx.y * 64;
    const int c0 = blockIdx.x * 64;
    const int tid = threadIdx.x;
    #pragma unroll
    for (int it = 0; it < 4; it++) {
        const int idx = it * 256 + tid;
        const int row = idx >> 4;
        const int c4  = (idx & 15) * 4;
        float4 f = *(const float4*)(in + (long long)(r0 + row) * Cc + c0 + c4);
        t[row][c4 + 0] = f.x; t[row][c4 + 1] = f.y;
        t[row][c4 + 2] = f.z; t[row][c4 + 3] = f.w;
    }
    __syncthreads();
    #pragma unroll
    for (int it = 0; it < 2; it++) {
        const int idx = it * 256 + tid;
        const int oc = idx >> 3;
        const int k8 = (idx & 7) * 8;
        __half h[8], l[8];
        #pragma unroll
        for (int j = 0; j < 8; j++) {
            const float f = t[k8 + j][oc];
            h[j] = __float2half(f);
            l[j] = __float2half(f - __half2float(h[j]));
        }
        const long long base = (long long)(c0 + oc) * R + r0 + k8;
        *(uint4*)(oh + base) = *(uint4*)h;
        *(uint4*)(ol + base) = *(uint4*)l;
    }
}

// ------------------------- mma.sync GEMM (split fp16, ldmatrix) -------------------
// C[M,N] = A[M,K] @ B[K,N]; A planes [M][K], B planes TRANSPOSED [N][K].
// T3=1: 3 terms. T3=0: 2 terms. MODE 0: fp32 out (+bias); MODE 1: fp16 hi/lo planes.
#define TSB 80
#define PLB 10240
#define BUFB 40960
#define GSMEM (2 * BUFB)

template<int T3, int MODE>
__global__ __launch_bounds__(256)
void gemm_mma(const __half* __restrict__ Ah, const __half* __restrict__ Al,
              const __half* __restrict__ Bh, const __half* __restrict__ Bl,
              const float* __restrict__ bias,
              float* __restrict__ Cf,
              __half* __restrict__ Ch, __half* __restrict__ Cl,
              int M, int Nn, int Kk,
              long long sA, long long sB, long long sC)
{
    extern __shared__ char sm[];
    const long long z = blockIdx.z;
    Ah += z * sA;
    if (T3) Al += z * sA;
    Bh += z * sB; Bl += z * sB;

    const int bRow = blockIdx.y * 128;
    const int bCol = blockIdx.x * 128;
    const int tid  = threadIdx.x;
    const int lane = tid & 31;
    const int wid  = tid >> 5;
    const int warpRow = (wid & 3) * 32;
    const int warpCol = (wid >> 2) * 64;
    const uint32_t sb = smem_u32(sm);

    float acc[2][8][4];
    #pragma unroll
    for (int i = 0; i < 2; i++)
        #pragma unroll
        for (int j = 0; j < 8; j++)
            #pragma unroll
            for (int r = 0; r < 4; r++) acc[i][j][r] = 0.f;

    const int nCh = Kk / 32;

    auto loadChunk = [&](int c, int buf) {
        const int k0 = c * 32;
        const uint32_t d = sb + buf * BUFB;
        #pragma unroll
        for (int s2 = 0; s2 < 2; s2++) {
            const int row = s2 * 64 + (tid >> 2);
            const int g   = tid & 3;
            const uint32_t doff = row * TSB + g * 16;
            const int ar = bRow + row;
            const int sz = (ar < M) ? 16 : 0;
            const long long aoff = (long long)((ar < M) ? ar : 0) * Kk + k0 + g * 8;
            cp16(d + doff, Ah + aoff, sz);
            if (T3) cp16(d + PLB + doff, Al + aoff, sz);
            const long long boff = (long long)(bCol + row) * Kk + k0 + g * 8;
            cp16(d + 2 * PLB + doff, Bh + boff, 16);
            cp16(d + 3 * PLB + doff, Bl + boff, 16);
        }
        CP_COMMIT();
    };

    // ldmatrix per-lane row components (fixed per thread)
    const int aRowSel = (lane & 15);          // A: rows 0..15 within m16 block
    const int aKHalf  = (lane >> 4) & 1;      // A: k 16-byte half
    const int bRowSel = (lane & 7) + ((lane >> 4) & 1) * 8;  // B: rows 0..15 within n16
    const int bKHalf  = (lane >> 3) & 1;      // B: k 16-byte half

    loadChunk(0, 0);
    for (int c = 0; c < nCh; c++) {
        const int buf = c & 1;
        if (c + 1 < nCh) { loadChunk(c + 1, buf ^ 1); CP_WAIT1(); }
        else             { CP_WAIT0(); }
        __syncthreads();

        const uint32_t aT = sb + buf * BUFB;
        const uint32_t bT = aT + 2 * PLB;

        #pragma unroll
        for (int s = 0; s < 2; s++) {
            const int kb = s * 32;
            uint32_t ah[2][4], al[2][4];
            #pragma unroll
            for (int i = 0; i < 2; i++) {
                const uint32_t ad = aT + (warpRow + i * 16 + aRowSel) * TSB
                                       + kb + aKHalf * 16;
                ldm_x4(ah[i], ad);
                if (T3) ldm_x4(al[i], ad + PLB);
            }
            #pragma unroll
            for (int jp = 0; jp < 4; jp++) {
                const uint32_t bd = bT + (warpCol + jp * 16 + bRowSel) * TSB
                                       + kb + bKHalf * 16;
                uint32_t bh[4], bl2[4];
                ldm_x4(bh,  bd);
                ldm_x4(bl2, bd + PLB);
                #pragma unroll
                for (int jj = 0; jj < 2; jj++) {
                    #pragma unroll
                    for (int i = 0; i < 2; i++) {
                        float* dacc = acc[i][2 * jp + jj];
                        mma_f16(dacc, ah[i], &bh[2 * jj]);
                        mma_f16(dacc, ah[i], &bl2[2 * jj]);
                        if (T3) mma_f16(dacc, al[i], &bh[2 * jj]);
                    }
                }
            }
        }
        __syncthreads();
    }

    // ------------- epilogue -------------
    const int rB = bRow + warpRow + (lane >> 2);
    if (MODE == 0) {
        float* C = Cf + z * sC;
        #pragma unroll
        for (int i = 0; i < 2; i++) {
            #pragma unroll
            for (int j = 0; j < 8; j++) {
                const int col = bCol + warpCol + j * 8 + (lane & 3) * 2;
                float bx = 0.f, by = 0.f;
                if (bias) { bx = bias[col]; by = bias[col + 1]; }
                const int r = rB + i * 16;
                if (r < M) {
                    float2 o = make_float2(acc[i][j][0] + bx, acc[i][j][1] + by);
                    *(float2*)(C + (long long)r * Nn + col) = o;
                }
                if (r + 8 < M) {
                    float2 o = make_float2(acc[i][j][2] + bx, acc[i][j][3] + by);
                    *(float2*)(C + (long long)(r + 8) * Nn + col) = o;
                }
            }
        }
    } else {
        __half* CH = Ch + z * sC;
        __half* CL = Cl + z * sC;
        #pragma unroll
        for (int i = 0; i < 2; i++) {
            #pragma unroll
            for (int j = 0; j < 8; j++) {
                const int col = bCol + warpCol + j * 8 + (lane & 3) * 2;
                #pragma unroll
                for (int half = 0; half < 2; half++) {
                    const int r = rB + i * 16 + half * 8;
                    if (r >= M) continue;
                    const float v0 = acc[i][j][2 * half + 0];
                    const float v1 = acc[i][j][2 * half + 1];
                    __half h0 = __float2half(v0);
                    __half h1 = __float2half(v1);
                    __half l0 = __float2half(v0 - __half2float(h0));
                    __half l1 = __float2half(v1 - __half2float(h1));
                    __half hp[2] = {h0, h1}, lp[2] = {l0, l1};
                    const long long base = (long long)r * Nn + col;
                    *(uint32_t*)(CH + base) = *(uint32_t*)hp;
                    *(uint32_t*)(CL + base) = *(uint32_t*)lp;
                }
            }
        }
    }
}

// ------------------------- chunk stats -------------------------
__device__ __forceinline__ float blk_reduce64(float x, float* red)
{
    const int d = threadIdx.x;
    #pragma unroll
    for (int o = 16; o > 0; o >>= 1)
        x += __shfl_down_sync(0xffffffffu, x, o);
    if ((d & 31) == 0) red[d >> 5] = x;
    __syncthreads();
    const float r = red[0] + red[1];
    __syncthreads();
    return r;
}

__global__ __launch_bounds__(64)
void chunk_stats(const float* __restrict__ q, const float* __restrict__ k,
                 const float* __restrict__ v,
                 const float* __restrict__ mqW, const float* __restrict__ mqb,
                 const float* __restrict__ mqg, const float* __restrict__ mqbe,
                 const float* __restrict__ mkW, const float* __restrict__ mkb,
                 const float* __restrict__ mkg, const float* __restrict__ mkbe,
                 float* __restrict__ rfk, float* __restrict__ beta)
{
    const int blk = blockIdx.x;
    const int c  = blk & 31;
    const int bh = blk >> 5;
    const int h  = bh % Hx;
    const int b  = bh / Hx;
    const int d  = threadIdx.x;

    __shared__ float qm[64], km[64], k0s[64], k1s[64], v0s[64], v1s[64];
    __shared__ float red[2];
    __shared__ float probs[2];

    {
        const float* qb = q + ((long long)(b * Nx + c * 32)) * Cx + h * DHx + d;
        float s = 0.f;
        #pragma unroll 8
        for (int i = 0; i < 32; i++) s += qb[(long long)i * Cx];
        qm[d] = s * (1.f / 32.f);
    }
    {
        const float* kb = k + ((long long)(b * Kx + c * 2)) * Cx + h * DHx + d;
        const float k0v = kb[0], k1v = kb[Cx];
        k0s[d] = k0v; k1s[d] = k1v;
        km[d]  = 0.5f * (k0v + k1v);
        const float* vb = v + ((long long)(b * Kx + c * 2)) * Cx + h * DHx + d;
        v0s[d] = vb[0]; v1s[d] = vb[Cx];
    }
    __syncthreads();

    float yq = mqb[d], yk = mkb[d];
    #pragma unroll 8
    for (int e = 0; e < 64; e++) {
        yq = fmaf(qm[e], mqW[e * 64 + d], yq);
        yk = fmaf(km[e], mkW[e * 64 + d], yk);
    }

    float m  = blk_reduce64(yq, red) * (1.f / 64.f);
    float dv = yq - m;
    float var = blk_reduce64(dv * dv, red) * (1.f / 64.f);
    const float qbar = dv * rsqrtf(var + LN_EPSx) * mqg[d] + mqbe[d];

    m  = blk_reduce64(yk, red) * (1.f / 64.f);
    dv = yk - m;
    var = blk_reduce64(dv * dv, red) * (1.f / 64.f);
    const float kbar = dv * rsqrtf(var + LN_EPSx) * mkg[d] + mkbe[d];

    rfk[((long long)bh * 32 + c) * 64 + d] = kbar;

    const float mu = 0.5f * (qbar + kbar);

    const float s0 = blk_reduce64(mu * k0s[d], red);
    const float n0 = blk_reduce64(k0s[d] * k0s[d], red);
    const float s1 = blk_reduce64(mu * k1s[d], red);
    const float n1 = blk_reduce64(k1s[d] * k1s[d], red);

    if (d == 0) {
        const float dn = 0.125f;
        const float l0 = dn * s0 - 0.5f * dn * n0;
        const float l1 = dn * s1 - 0.5f * dn * n1;
        const float mx = fmaxf(l0, l1);
        const float e0 = expf(l0 - mx);
        const float e1 = expf(l1 - mx);
        const float inv = 1.f / (e0 + e1);
        probs[0] = e0 * inv;
        probs[1] = e1 * inv;
    }
    __syncthreads();

    beta[((long long)bh * 32 + c) * 64 + d] = probs[0] * v0s[d] + probs[1] * v1s[d];
}

// ------------------------- attention (fp16 hi output) -------------------------
__global__ __launch_bounds__(256)
void attn_kernel(const float* __restrict__ q, const float* __restrict__ k,
                 const float* __restrict__ v,
                 const float* __restrict__ rfk, const float* __restrict__ betag,
                 __half* __restrict__ outH)
{
    const int blk = blockIdx.x;
    const int w  = blk & 31;
    const int bh = blk >> 5;
    const int h  = bh % Hx;
    const int b  = bh / Hx;

    __shared__ float qs [32][65];
    __shared__ float kbs[32][64];
    __shared__ float bes[32][64];
    __shared__ float wks[2][64];
    __shared__ float wvs[2][64];
    __shared__ float lg [32][35];

    const int t = threadIdx.x;

    for (int idx = t; idx < 2048; idx += 256) {
        const int i = idx >> 6, d = idx & 63;
        qs [i][d] = q    [((long long)(b * Nx + w * 32 + i)) * Cx + h * DHx + d];
        kbs[i][d] = rfk  [((long long)bh * 32 + i) * 64 + d];
        bes[i][d] = betag[((long long)bh * 32 + i) * 64 + d];
    }
    if (t < 128) {
        const int j = t >> 6, d = t & 63;
        wks[j][d] = k[((long long)(b * Kx + w * 2 + j)) * Cx + h * DHx + d];
        wvs[j][d] = v[((long long)(b * Kx + w * 2 + j)) * Cx + h * DHx + d];
    }
    __syncthreads();

    {
        const int i   = t & 31;
        const int sl0 = t >> 5;
        for (int slot = sl0; slot < 34; slot += 8) {
            const float* kv = (slot < 2) ? &wks[slot][0] : &kbs[slot - 2][0];
            float s = 0.f;
            #pragma unroll
            for (int e = 0; e < 64; e++) s = fmaf(qs[i][e], kv[e], s);
            lg[i][slot] = s * SCALEx;
        }
    }
    __syncthreads();

    if (t < 32) {
        float mx = -1e30f;
        #pragma unroll
        for (int s = 0; s < 34; s++) mx = fmaxf(mx, lg[t][s]);
        float sum = 0.f;
        #pragma unroll
        for (int s = 0; s < 34; s++) { const float e = expf(lg[t][s] - mx); lg[t][s] = e; sum += e; }
        const float inv = 1.f / sum;
        #pragma unroll
        for (int s = 0; s < 34; s++) lg[t][s] *= inv;
    }
    __syncthreads();

    const int d = t & 63;
    #pragma unroll
    for (int p = 0; p < 8; p++) {
        const int ii = p * 4 + (t >> 6);
        float acc = lg[ii][0] * wvs[0][d] + lg[ii][1] * wvs[1][d];
        #pragma unroll
        for (int c2 = 0; c2 < 32; c2++)
            acc = fmaf(lg[ii][2 + c2], bes[c2][d], acc);
        const long long ro = ((long long)(b * Nx + w * 32 + ii)) * Cx + h * DHx + d;
        outH[ro] = __float2half(acc);
    }
}

// ------------------------- launch -------------------------
extern "C" void kernel_launch(void* const* d_in, const int* in_sizes, int n_in,
                              void* d_out, int out_size)
{
    const float* query = (const float*)d_in[0];
    const float* key   = (const float*)d_in[1];
    const float* value = (const float*)d_in[2];
    const float* Wq    = (const float*)d_in[3];
    const float* bq    = (const float*)d_in[4];
    const float* Wk    = (const float*)d_in[5];
    const float* bk    = (const float*)d_in[6];
    const float* Wv    = (const float*)d_in[7];
    const float* bv    = (const float*)d_in[8];
    const float* Wo    = (const float*)d_in[9];
    const float* bo    = (const float*)d_in[10];
    const float* kds   = (const float*)d_in[11];
    const float* vds   = (const float*)d_in[12];
    const float* mqW   = (const float*)d_in[13];
    const float* mqb   = (const float*)d_in[14];
    const float* mqg   = (const float*)d_in[15];
    const float* mqbe  = (const float*)d_in[16];
    const float* mkW   = (const float*)d_in[17];
    const float* mkb   = (const float*)d_in[18];
    const float* mkg   = (const float*)d_in[19];
    const float* mkbe  = (const float*)d_in[20];
    float* out = (float*)d_out;

    float *q, *kk, *vv, *rfk, *beta;
    cudaGetSymbolAddress((void**)&q,    g_q);
    cudaGetSymbolAddress((void**)&kk,   g_k);
    cudaGetSymbolAddress((void**)&vv,   g_v);
    cudaGetSymbolAddress((void**)&rfk,  g_rfk);
    cudaGetSymbolAddress((void**)&beta, g_beta);

    __half *qH, *attH, *kdsH, *kdsL, *vdsH, *vdsL;
    __half *keyTH, *keyTL, *valTH, *valTL, *kdH, *kdL, *vdH, *vdL;
    __half *wqTH, *wqTL, *wkTH, *wkTL, *wvTH, *wvTL, *woTH, *woTL;
    cudaGetSymbolAddress((void**)&qH,    g_qH);
    cudaGetSymbolAddress((void**)&attH,  g_attH);
    cudaGetSymbolAddress((void**)&kdsH,  g_kdsH);
    cudaGetSymbolAddress((void**)&kdsL,  g_kdsL);
    cudaGetSymbolAddress((void**)&vdsH,  g_vdsH);
    cudaGetSymbolAddress((void**)&vdsL,  g_vdsL);
    cudaGetSymbolAddress((void**)&keyTH, g_keyTH);
    cudaGetSymbolAddress((void**)&keyTL, g_keyTL);
    cudaGetSymbolAddress((void**)&valTH, g_valTH);
    cudaGetSymbolAddress((void**)&valTL, g_valTL);
    cudaGetSymbolAddress((void**)&kdH,   g_kdH);
    cudaGetSymbolAddress((void**)&kdL,   g_kdL);
    cudaGetSymbolAddress((void**)&vdH,   g_vdH);
    cudaGetSymbolAddress((void**)&vdL,   g_vdL);
    cudaGetSymbolAddress((void**)&wqTH,  g_wqTH);
    cudaGetSymbolAddress((void**)&wqTL,  g_wqTL);
    cudaGetSymbolAddress((void**)&wkTH,  g_wkTH);
    cudaGetSymbolAddress((void**)&wkTL,  g_wkTL);
    cudaGetSymbolAddress((void**)&wvTH,  g_wvTH);
    cudaGetSymbolAddress((void**)&wvTL,  g_wvTL);
    cudaGetSymbolAddress((void**)&woTH,  g_woTH);
    cudaGetSymbolAddress((void**)&woTL,  g_woTL);

    cudaFuncSetAttribute(gemm_mma<0, 0>, cudaFuncAttributeMaxDynamicSharedMemorySize, GSMEM);
    cudaFuncSetAttribute(gemm_mma<1, 0>, cudaFuncAttributeMaxDynamicSharedMemorySize, GSMEM);
    cudaFuncSetAttribute(gemm_mma<1, 1>, cudaFuncAttributeMaxDynamicSharedMemorySize, GSMEM);

    // ---- prep needed for q-projection ----
    {
        long long t4 = (long long)Bx * Nx * Cx / 4;
        convert16<<<(unsigned)((t4 + 255) / 256), 256>>>(query, qH, nullptr, t4);
    }
    transpose_split16<<<dim3(Cx / 64, Cx / 64, 1), 256>>>(Wq, wqTH, wqTL, Cx, Cx, 0, 0);
    {
        long long t4 = (long long)Kx * Nx / 4;
        convert16<<<(unsigned)((t4 + 255) / 256), 256>>>(kds, kdsH, kdsL, t4);
        convert16<<<(unsigned)((t4 + 255) / 256), 256>>>(vds, vdsH, vdsL, t4);
    }
    transpose_split16<<<dim3(Cx / 64, Cx / 64, 1), 256>>>(Wk, wkTH, wkTL, Cx, Cx, 0, 0);

    // q = query @ Wq + bq : M=65536, N=768, K=768 -> fp32 (2-term)
    gemm_mma<0, 0><<<dim3(Cx / 128, (Bx * Nx) / 128, 1), 256, GSMEM>>>(
        qH, nullptr, wqTH, wqTL, bq, q, nullptr, nullptr,
        Bx * Nx, Cx, Cx, 0, 0, 0);

    // ---- remaining prep ----
    transpose_split16<<<dim3(Cx / 64, Cx / 64, 1), 256>>>(Wv, wvTH, wvTL, Cx, Cx, 0, 0);
    transpose_split16<<<dim3(Cx / 64, Cx / 64, 1), 256>>>(Wo, woTH, woTL, Cx, Cx, 0, 0);
    transpose_split16<<<dim3(Cx / 64, Nx / 64, Bx), 256>>>(key, keyTH, keyTL, Nx, Cx,
        (long long)Nx * Cx, (long long)Cx * Nx);
    transpose_split16<<<dim3(Cx / 64, Nx / 64, Bx), 256>>>(value, valTH, valTL, Nx, Cx,
        (long long)Nx * Cx, (long long)Cx * Nx);

    // key_d[b] = kds @ key[b]; val_d[b] = vds @ value[b] : M=64, N=768, K=1024 (3-term)
    gemm_mma<1, 1><<<dim3(Cx / 128, 1, Bx), 256, GSMEM>>>(
        kdsH, kdsL, keyTH, keyTL, nullptr, nullptr, kdH, kdL,
        Kx, Cx, Nx, 0, (long long)Cx * Nx, (long long)Kx * Cx);
    gemm_mma<1, 1><<<dim3(Cx / 128, 1, Bx), 256, GSMEM>>>(
        vdsH, vdsL, valTH, valTL, nullptr, nullptr, vdH, vdL,
        Kx, Cx, Nx, 0, (long long)Cx * Nx, (long long)Kx * Cx);

    // k = key_d @ Wk + bk ; v = val_d @ Wv + bv : M=4096, N=768, K=768 (3-term)
    gemm_mma<1, 0><<<dim3(Cx / 128, (Bx * Kx) / 128, 1), 256, GSMEM>>>(
        kdH, kdL, wkTH, wkTL, bk, kk, nullptr, nullptr,
        Bx * Kx, Cx, Cx, 0, 0, 0);
    gemm_mma<1, 0><<<dim3(Cx / 128, (Bx * Kx) / 128, 1), 256, GSMEM>>>(
        vdH, vdL, wvTH, wvTL, bv, vv, nullptr, nullptr,
        Bx * Kx, Cx, Cx, 0, 0, 0);

    // chunk summaries + attention
    chunk_stats<<<Bx * Hx * 32, 64>>>(q, kk, vv,
                                      mqW, mqb, mqg, mqbe,
                                      mkW, mkb, mkg, mkbe,
                                      rfk, beta);
    attn_kernel<<<Bx * Hx * 32, 256>>>(q, kk, vv, rfk, beta, attH);

    // out = att @ Wo + bo : M=65536, N=768, K=768 -> fp32 (2-term)
    gemm_mma<0, 0><<<dim3(Cx / 128, (Bx * Nx) / 128, 1), 256, GSMEM>>>(
        attH, nullptr, woTH, woTL, bo, out, nullptr, nullptr,
        Bx * Nx, Cx, Cx, 0, 0, 0);
}

// round 10
// speedup vs baseline: 1.0162x; 1.0162x over previous
#include <cuda_runtime.h>
#include <cuda_fp16.h>
#include <math.h>
#include <stdint.h>

// Problem constants
#define Bx   64
#define Nx   1024
#define Cx   768
#define Hx   12
#define DHx  64
#define Kx   64
#define SCALEx 0.125f
#define LN_EPSx 1e-6f

// ------------------------- device scratch -------------------------
__device__ float g_q   [(long long)Bx * Nx * Cx];
__device__ float g_k   [(long long)Bx * Kx * Cx];
__device__ float g_v   [(long long)Bx * Kx * Cx];
__device__ float g_rfk [(long long)Bx * Hx * 32 * DHx];
__device__ float g_beta[(long long)Bx * Hx * 32 * DHx];

// fp16 planes (row-major)
__device__ __half g_qH   [(long long)Bx * Nx * Cx];
__device__ __half g_attH [(long long)Bx * Nx * Cx];
__device__ __half g_kdsH [Kx * Nx];
__device__ __half g_kdsL [Kx * Nx];
__device__ __half g_vdsH [Kx * Nx];
__device__ __half g_vdsL [Kx * Nx];
__device__ __half g_keyTH[(long long)Bx * Cx * Nx];
__device__ __half g_keyTL[(long long)Bx * Cx * Nx];
__device__ __half g_valTH[(long long)Bx * Cx * Nx];
__device__ __half g_valTL[(long long)Bx * Cx * Nx];
__device__ __half g_kdH  [(long long)Bx * Kx * Cx];
__device__ __half g_kdL  [(long long)Bx * Kx * Cx];
__device__ __half g_vdH  [(long long)Bx * Kx * Cx];
__device__ __half g_vdL  [(long long)Bx * Kx * Cx];
__device__ __half g_wqTH [Cx * Cx];
__device__ __half g_wqTL [Cx * Cx];
__device__ __half g_wkTH [Cx * Cx];
__device__ __half g_wkTL [Cx * Cx];
__device__ __half g_wvTH [Cx * Cx];
__device__ __half g_wvTL [Cx * Cx];
__device__ __half g_woTH [Cx * Cx];
__device__ __half g_woTL [Cx * Cx];

// ------------------------- helpers -------------------------
__device__ __forceinline__ uint32_t smem_u32(const void* p) {
    uint32_t a;
    asm("{ .reg .u64 t; cvta.to.shared.u64 t, %1; cvt.u32.u64 %0, t; }" : "=r"(a) : "l"(p));
    return a;
}
__device__ __forceinline__ void cp16(uint32_t dst, const void* src, int srcsz) {
    asm volatile("cp.async.cg.shared.global [%0], [%1], 16, %2;"
                 :: "r"(dst), "l"(src), "r"(srcsz) : "memory");
}
#define CP_COMMIT() asm volatile("cp.async.commit_group;" ::: "memory")
#define CP_WAIT1()  asm volatile("cp.async.wait_group 1;" ::: "memory")
#define CP_WAIT0()  asm volatile("cp.async.wait_group 0;" ::: "memory")

__device__ __forceinline__ void ldm_x4(uint32_t* r, uint32_t a) {
    asm volatile("ldmatrix.sync.aligned.m8n8.x4.shared.b16 {%0,%1,%2,%3}, [%4];"
                 : "=r"(r[0]), "=r"(r[1]), "=r"(r[2]), "=r"(r[3]) : "r"(a));
}
__device__ __forceinline__ void mma_f16(float* d, const uint32_t* a, const uint32_t* b) {
    asm volatile("mma.sync.aligned.m16n8k16.row.col.f32.f16.f16.f32 "
                 "{%0,%1,%2,%3},{%4,%5,%6,%7},{%8,%9},{%0,%1,%2,%3};"
                 : "+f"(d[0]), "+f"(d[1]), "+f"(d[2]), "+f"(d[3])
                 : "r"(a[0]), "r"(a[1]), "r"(a[2]), "r"(a[3]), "r"(b[0]), "r"(b[1]));
}

// ------------------------- convert (row-major, hi [+lo]) -------------------------
__global__ __launch_bounds__(256)
void convert16(const float* __restrict__ in,
               __half* __restrict__ oh, __half* __restrict__ ol,
               long long total4)
{
    const long long g = (long long)blockIdx.x * 256 + threadIdx.x;
    if (g >= total4) return;
    float4 f = ((const float4*)in)[g];
    __half h[4];
    h[0] = __float2half(f.x); h[1] = __float2half(f.y);
    h[2] = __float2half(f.z); h[3] = __float2half(f.w);
    *(uint2*)(oh + g * 4) = *(uint2*)h;
    if (ol) {
        __half l[4];
        l[0] = __float2half(f.x - __half2float(h[0]));
        l[1] = __float2half(f.y - __half2float(h[1]));
        l[2] = __float2half(f.z - __half2float(h[2]));
        l[3] = __float2half(f.w - __half2float(h[3]));
        *(uint2*)(ol + g * 4) = *(uint2*)l;
    }
}

// ------------------------- transpose + split ------------
__global__ __launch_bounds__(256)
void transpose_split16(const float* __restrict__ in,
                       __half* __restrict__ oh, __half* __restrict__ ol,
                       int R, int Cc, long long sIn, long long sOut)
{
    __shared__ float t[64][65];
    in += (long long)blockIdx.z * sIn;
    oh += (long long)blockIdx.z * sOut;
    ol += (long long)blockIdx.z * sOut;
    const int r0 = blockIdx.y * 64;
    const int c0 = blockIdx.x * 64;
    const int tid = threadIdx.x;
    #pragma unroll
    for (int it = 0; it < 4; it++) {
        const int idx = it * 256 + tid;
        const int row = idx >> 4;
        const int c4  = (idx & 15) * 4;
        float4 f = *(const float4*)(in + (long long)(r0 + row) * Cc + c0 + c4);
        t[row][c4 + 0] = f.x; t[row][c4 + 1] = f.y;
        t[row][c4 + 2] = f.z; t[row][c4 + 3] = f.w;
    }
    __syncthreads();
    #pragma unroll
    for (int it = 0; it < 2; it++) {
        const int idx = it * 256 + tid;
        const int oc = idx >> 3;
        const int k8 = (idx & 7) * 8;
        __half h[8], l[8];
        #pragma unroll
        for (int j = 0; j < 8; j++) {
            const float f = t[k8 + j][oc];
            h[j] = __float2half(f);
            l[j] = __float2half(f - __half2float(h[j]));
        }
        const long long base = (long long)(c0 + oc) * R + r0 + k8;
        *(uint4*)(oh + base) = *(uint4*)h;
        *(uint4*)(ol + base) = *(uint4*)l;
    }
}

// ------------------------- mma.sync GEMM (split fp16, ldmatrix) -------------------
#define TSB 80
#define PLB 10240
#define BUFB 40960
#define GSMEM (2 * BUFB)

template<int T3, int MODE>
__global__ __launch_bounds__(256)
void gemm_mma(const __half* __restrict__ Ah, const __half* __restrict__ Al,
              const __half* __restrict__ Bh, const __half* __restrict__ Bl,
              const float* __restrict__ bias,
              float* __restrict__ Cf,
              __half* __restrict__ Ch, __half* __restrict__ Cl,
              int M, int Nn, int Kk,
              long long sA, long long sB, long long sC)
{
    extern __shared__ char sm[];
    const long long z = blockIdx.z;
    Ah += z * sA;
    if (T3) Al += z * sA;
    Bh += z * sB; Bl += z * sB;

    const int bRow = blockIdx.y * 128;
    const int bCol = blockIdx.x * 128;
    const int tid  = threadIdx.x;
    const int lane = tid & 31;
    const int wid  = tid >> 5;
    const int warpRow = (wid & 3) * 32;
    const int warpCol = (wid >> 2) * 64;
    const uint32_t sb = smem_u32(sm);

    float acc[2][8][4];
    #pragma unroll
    for (int i = 0; i < 2; i++)
        #pragma unroll
        for (int j = 0; j < 8; j++)
            #pragma unroll
            for (int r = 0; r < 4; r++) acc[i][j][r] = 0.f;

    const int nCh = Kk / 32;

    auto loadChunk = [&](int c, int buf) {
        const int k0 = c * 32;
        const uint32_t d = sb + buf * BUFB;
        #pragma unroll
        for (int s2 = 0; s2 < 2; s2++) {
            const int row = s2 * 64 + (tid >> 2);
            const int g   = tid & 3;
            const uint32_t doff = row * TSB + g * 16;
            const int ar = bRow + row;
            const int sz = (ar < M) ? 16 : 0;
            const long long aoff = (long long)((ar < M) ? ar : 0) * Kk + k0 + g * 8;
            cp16(d + doff, Ah + aoff, sz);
            if (T3) cp16(d + PLB + doff, Al + aoff, sz);
            const long long boff = (long long)(bCol + row) * Kk + k0 + g * 8;
            cp16(d + 2 * PLB + doff, Bh + boff, 16);
            cp16(d + 3 * PLB + doff, Bl + boff, 16);
        }
        CP_COMMIT();
    };

    const int aRowSel = (lane & 15);
    const int aKHalf  = (lane >> 4) & 1;
    const int bRowSel = (lane & 7) + ((lane >> 4) & 1) * 8;
    const int bKHalf  = (lane >> 3) & 1;

    loadChunk(0, 0);
    for (int c = 0; c < nCh; c++) {
        const int buf = c & 1;
        if (c + 1 < nCh) { loadChunk(c + 1, buf ^ 1); CP_WAIT1(); }
        else             { CP_WAIT0(); }
        __syncthreads();

        const uint32_t aT = sb + buf * BUFB;
        const uint32_t bT = aT + 2 * PLB;

        #pragma unroll
        for (int s = 0; s < 2; s++) {
            const int kb = s * 32;
            uint32_t ah[2][4], al[2][4];
            #pragma unroll
            for (int i = 0; i < 2; i++) {
                const uint32_t ad = aT + (warpRow + i * 16 + aRowSel) * TSB
                                       + kb + aKHalf * 16;
                ldm_x4(ah[i], ad);
                if (T3) ldm_x4(al[i], ad + PLB);
            }
            #pragma unroll
            for (int jp = 0; jp < 4; jp++) {
                const uint32_t bd = bT + (warpCol + jp * 16 + bRowSel) * TSB
                                       + kb + bKHalf * 16;
                uint32_t bh[4], bl2[4];
                ldm_x4(bh,  bd);
                ldm_x4(bl2, bd + PLB);
                #pragma unroll
                for (int jj = 0; jj < 2; jj++) {
                    #pragma unroll
                    for (int i = 0; i < 2; i++) {
                        float* dacc = acc[i][2 * jp + jj];
                        mma_f16(dacc, ah[i], &bh[2 * jj]);
                        mma_f16(dacc, ah[i], &bl2[2 * jj]);
                        if (T3) mma_f16(dacc, al[i], &bh[2 * jj]);
                    }
                }
            }
        }
        __syncthreads();
    }

    // ------------- epilogue -------------
    const int rB = bRow + warpRow + (lane >> 2);
    if (MODE == 0) {
        float* C = Cf + z * sC;
        #pragma unroll
        for (int i = 0; i < 2; i++) {
            #pragma unroll
            for (int j = 0; j < 8; j++) {
                const int col = bCol + warpCol + j * 8 + (lane & 3) * 2;
                float bx = 0.f, by = 0.f;
                if (bias) { bx = bias[col]; by = bias[col + 1]; }
                const int r = rB + i * 16;
                if (r < M) {
                    float2 o = make_float2(acc[i][j][0] + bx, acc[i][j][1] + by);
                    *(float2*)(C + (long long)r * Nn + col) = o;
                }
                if (r + 8 < M) {
                    float2 o = make_float2(acc[i][j][2] + bx, acc[i][j][3] + by);
                    *(float2*)(C + (long long)(r + 8) * Nn + col) = o;
                }
            }
        }
    } else {
        __half* CH = Ch + z * sC;
        __half* CL = Cl + z * sC;
        #pragma unroll
        for (int i = 0; i < 2; i++) {
            #pragma unroll
            for (int j = 0; j < 8; j++) {
                const int col = bCol + warpCol + j * 8 + (lane & 3) * 2;
                #pragma unroll
                for (int half = 0; half < 2; half++) {
                    const int r = rB + i * 16 + half * 8;
                    if (r >= M) continue;
                    const float v0 = acc[i][j][2 * half + 0];
                    const float v1 = acc[i][j][2 * half + 1];
                    __half h0 = __float2half(v0);
                    __half h1 = __float2half(v1);
                    __half l0 = __float2half(v0 - __half2float(h0));
                    __half l1 = __float2half(v1 - __half2float(h1));
                    __half hp[2] = {h0, h1}, lp[2] = {l0, l1};
                    const long long base = (long long)r * Nn + col;
                    *(uint32_t*)(CH + base) = *(uint32_t*)hp;
                    *(uint32_t*)(CL + base) = *(uint32_t*)lp;
                }
            }
        }
    }
}

// ------------------------- chunk stats -------------------------
__device__ __forceinline__ float blk_reduce64(float x, float* red)
{
    const int d = threadIdx.x;
    #pragma unroll
    for (int o = 16; o > 0; o >>= 1)
        x += __shfl_down_sync(0xffffffffu, x, o);
    if ((d & 31) == 0) red[d >> 5] = x;
    __syncthreads();
    const float r = red[0] + red[1];
    __syncthreads();
    return r;
}

__global__ __launch_bounds__(64)
void chunk_stats(const float* __restrict__ q, const float* __restrict__ k,
                 const float* __restrict__ v,
                 const float* __restrict__ mqW, const float* __restrict__ mqb,
                 const float* __restrict__ mqg, const float* __restrict__ mqbe,
                 const float* __restrict__ mkW, const float* __restrict__ mkb,
                 const float* __restrict__ mkg, const float* __restrict__ mkbe,
                 float* __restrict__ rfk, float* __restrict__ beta)
{
    const int blk = blockIdx.x;
    const int c  = blk & 31;
    const int bh = blk >> 5;
    const int h  = bh % Hx;
    const int b  = bh / Hx;
    const int d  = threadIdx.x;

    __shared__ float qm[64], km[64], k0s[64], k1s[64], v0s[64], v1s[64];
    __shared__ float red[2];
    __shared__ float probs[2];

    {
        const float* qb = q + ((long long)(b * Nx + c * 32)) * Cx + h * DHx + d;
        float s = 0.f;
        #pragma unroll 8
        for (int i = 0; i < 32; i++) s += qb[(long long)i * Cx];
        qm[d] = s * (1.f / 32.f);
    }
    {
        const float* kb = k + ((long long)(b * Kx + c * 2)) * Cx + h * DHx + d;
        const float k0v = kb[0], k1v = kb[Cx];
        k0s[d] = k0v; k1s[d] = k1v;
        km[d]  = 0.5f * (k0v + k1v);
        const float* vb = v + ((long long)(b * Kx + c * 2)) * Cx + h * DHx + d;
        v0s[d] = vb[0]; v1s[d] = vb[Cx];
    }
    __syncthreads();

    float yq = mqb[d], yk = mkb[d];
    #pragma unroll 8
    for (int e = 0; e < 64; e++) {
        yq = fmaf(qm[e], mqW[e * 64 + d], yq);
        yk = fmaf(km[e], mkW[e * 64 + d], yk);
    }

    float m  = blk_reduce64(yq, red) * (1.f / 64.f);
    float dv = yq - m;
    float var = blk_reduce64(dv * dv, red) * (1.f / 64.f);
    const float qbar = dv * rsqrtf(var + LN_EPSx) * mqg[d] + mqbe[d];

    m  = blk_reduce64(yk, red) * (1.f / 64.f);
    dv = yk - m;
    var = blk_reduce64(dv * dv, red) * (1.f / 64.f);
    const float kbar = dv * rsqrtf(var + LN_EPSx) * mkg[d] + mkbe[d];

    rfk[((long long)bh * 32 + c) * 64 + d] = kbar;

    const float mu = 0.5f * (qbar + kbar);

    const float s0 = blk_reduce64(mu * k0s[d], red);
    const float n0 = blk_reduce64(k0s[d] * k0s[d], red);
    const float s1 = blk_reduce64(mu * k1s[d], red);
    const float n1 = blk_reduce64(k1s[d] * k1s[d], red);

    if (d == 0) {
        const float dn = 0.125f;
        const float l0 = dn * s0 - 0.5f * dn * n0;
        const float l1 = dn * s1 - 0.5f * dn * n1;
        const float mx = fmaxf(l0, l1);
        const float e0 = expf(l0 - mx);
        const float e1 = expf(l1 - mx);
        const float inv = 1.f / (e0 + e1);
        probs[0] = e0 * inv;
        probs[1] = e1 * inv;
    }
    __syncthreads();

    beta[((long long)bh * 32 + c) * 64 + d] = probs[0] * v0s[d] + probs[1] * v1s[d];
}

// ------------------------- attention (fp16 hi output) -------------------------
__global__ __launch_bounds__(256)
void attn_kernel(const float* __restrict__ q, const float* __restrict__ k,
                 const float* __restrict__ v,
                 const float* __restrict__ rfk, const float* __restrict__ betag,
                 __half* __restrict__ outH)
{
    const int blk = blockIdx.x;
    const int w  = blk & 31;
    const int bh = blk >> 5;
    const int h  = bh % Hx;
    const int b  = bh / Hx;

    __shared__ float qs [32][65];
    __shared__ float kbs[32][64];
    __shared__ float bes[32][64];
    __shared__ float wks[2][64];
    __shared__ float wvs[2][64];
    __shared__ float lg [32][35];

    const int t = threadIdx.x;

    for (int idx = t; idx < 2048; idx += 256) {
        const int i = idx >> 6, d = idx & 63;
        qs [i][d] = q    [((long long)(b * Nx + w * 32 + i)) * Cx + h * DHx + d];
        kbs[i][d] = rfk  [((long long)bh * 32 + i) * 64 + d];
        bes[i][d] = betag[((long long)bh * 32 + i) * 64 + d];
    }
    if (t < 128) {
        const int j = t >> 6, d = t & 63;
        wks[j][d] = k[((long long)(b * Kx + w * 2 + j)) * Cx + h * DHx + d];
        wvs[j][d] = v[((long long)(b * Kx + w * 2 + j)) * Cx + h * DHx + d];
    }
    __syncthreads();

    {
        const int i   = t & 31;
        const int sl0 = t >> 5;
        for (int slot = sl0; slot < 34; slot += 8) {
            const float* kv = (slot < 2) ? &wks[slot][0] : &kbs[slot - 2][0];
            float s = 0.f;
            #pragma unroll
            for (int e = 0; e < 64; e++) s = fmaf(qs[i][e], kv[e], s);
            lg[i][slot] = s * SCALEx;
        }
    }
    __syncthreads();

    if (t < 32) {
        float mx = -1e30f;
        #pragma unroll
        for (int s = 0; s < 34; s++) mx = fmaxf(mx, lg[t][s]);
        float sum = 0.f;
        #pragma unroll
        for (int s = 0; s < 34; s++) { const float e = expf(lg[t][s] - mx); lg[t][s] = e; sum += e; }
        const float inv = 1.f / sum;
        #pragma unroll
        for (int s = 0; s < 34; s++) lg[t][s] *= inv;
    }
    __syncthreads();

    const int d = t & 63;
    #pragma unroll
    for (int p = 0; p < 8; p++) {
        const int ii = p * 4 + (t >> 6);
        float acc = lg[ii][0] * wvs[0][d] + lg[ii][1] * wvs[1][d];
        #pragma unroll
        for (int c2 = 0; c2 < 32; c2++)
            acc = fmaf(lg[ii][2 + c2], bes[c2][d], acc);
        const long long ro = ((long long)(b * Nx + w * 32 + ii)) * Cx + h * DHx + d;
        outH[ro] = __float2half(acc);
    }
}

// ------------------------- launch -------------------------
static cudaStream_t g_s1 = nullptr;
static cudaEvent_t  g_evA = nullptr, g_evB = nullptr;

extern "C" void kernel_launch(void* const* d_in, const int* in_sizes, int n_in,
                              void* d_out, int out_size)
{
    const float* query = (const float*)d_in[0];
    const float* key   = (const float*)d_in[1];
    const float* value = (const float*)d_in[2];
    const float* Wq    = (const float*)d_in[3];
    const float* bq    = (const float*)d_in[4];
    const float* Wk    = (const float*)d_in[5];
    const float* bk    = (const float*)d_in[6];
    const float* Wv    = (const float*)d_in[7];
    const float* bv    = (const float*)d_in[8];
    const float* Wo    = (const float*)d_in[9];
    const float* bo    = (const float*)d_in[10];
    const float* kds   = (const float*)d_in[11];
    const float* vds   = (const float*)d_in[12];
    const float* mqW   = (const float*)d_in[13];
    const float* mqb   = (const float*)d_in[14];
    const float* mqg   = (const float*)d_in[15];
    const float* mqbe  = (const float*)d_in[16];
    const float* mkW   = (const float*)d_in[17];
    const float* mkb   = (const float*)d_in[18];
    const float* mkg   = (const float*)d_in[19];
    const float* mkbe  = (const float*)d_in[20];
    float* out = (float*)d_out;

    if (!g_s1) {
        cudaStreamCreateWithFlags(&g_s1, cudaStreamNonBlocking);
        cudaEventCreateWithFlags(&g_evA, cudaEventDisableTiming);
        cudaEventCreateWithFlags(&g_evB, cudaEventDisableTiming);
    }

    float *q, *kk, *vv, *rfk, *beta;
    cudaGetSymbolAddress((void**)&q,    g_q);
    cudaGetSymbolAddress((void**)&kk,   g_k);
    cudaGetSymbolAddress((void**)&vv,   g_v);
    cudaGetSymbolAddress((void**)&rfk,  g_rfk);
    cudaGetSymbolAddress((void**)&beta, g_beta);

    __half *qH, *attH, *kdsH, *kdsL, *vdsH, *vdsL;
    __half *keyTH, *keyTL, *valTH, *valTL, *kdH, *kdL, *vdH, *vdL;
    __half *wqTH, *wqTL, *wkTH, *wkTL, *wvTH, *wvTL, *woTH, *woTL;
    cudaGetSymbolAddress((void**)&qH,    g_qH);
    cudaGetSymbolAddress((void**)&attH,  g_attH);
    cudaGetSymbolAddress((void**)&kdsH,  g_kdsH);
    cudaGetSymbolAddress((void**)&kdsL,  g_kdsL);
    cudaGetSymbolAddress((void**)&vdsH,  g_vdsH);
    cudaGetSymbolAddress((void**)&vdsL,  g_vdsL);
    cudaGetSymbolAddress((void**)&keyTH, g_keyTH);
    cudaGetSymbolAddress((void**)&keyTL, g_keyTL);
    cudaGetSymbolAddress((void**)&valTH, g_valTH);
    cudaGetSymbolAddress((void**)&valTL, g_valTL);
    cudaGetSymbolAddress((void**)&kdH,   g_kdH);
    cudaGetSymbolAddress((void**)&kdL,   g_kdL);
    cudaGetSymbolAddress((void**)&vdH,   g_vdH);
    cudaGetSymbolAddress((void**)&vdL,   g_vdL);
    cudaGetSymbolAddress((void**)&wqTH,  g_wqTH);
    cudaGetSymbolAddress((void**)&wqTL,  g_wqTL);
    cudaGetSymbolAddress((void**)&wkTH,  g_wkTH);
    cudaGetSymbolAddress((void**)&wkTL,  g_wkTL);
    cudaGetSymbolAddress((void**)&wvTH,  g_wvTH);
    cudaGetSymbolAddress((void**)&wvTL,  g_wvTL);
    cudaGetSymbolAddress((void**)&woTH,  g_woTH);
    cudaGetSymbolAddress((void**)&woTL,  g_woTL);

    cudaFuncSetAttribute(gemm_mma<0, 0>, cudaFuncAttributeMaxDynamicSharedMemorySize, GSMEM);
    cudaFuncSetAttribute(gemm_mma<1, 0>, cudaFuncAttributeMaxDynamicSharedMemorySize, GSMEM);
    cudaFuncSetAttribute(gemm_mma<1, 1>, cudaFuncAttributeMaxDynamicSharedMemorySize, GSMEM);

    // ================= fork: side stream handles the KV chain =================
    cudaEventRecord(g_evA, 0);
    cudaStreamWaitEvent(g_s1, g_evA, 0);

    // ---- side stream (g_s1): KV chain ----
    {
        long long t4 = (long long)Kx * Nx / 4;
        convert16<<<(unsigned)((t4 + 255) / 256), 256, 0, g_s1>>>(kds, kdsH, kdsL, t4);
        convert16<<<(unsigned)((t4 + 255) / 256), 256, 0, g_s1>>>(vds, vdsH, vdsL, t4);
    }
    transpose_split16<<<dim3(Cx / 64, Cx / 64, 1), 256, 0, g_s1>>>(Wk, wkTH, wkTL, Cx, Cx, 0, 0);
    transpose_split16<<<dim3(Cx / 64, Cx / 64, 1), 256, 0, g_s1>>>(Wv, wvTH, wvTL, Cx, Cx, 0, 0);
    transpose_split16<<<dim3(Cx / 64, Nx / 64, Bx), 256, 0, g_s1>>>(key, keyTH, keyTL, Nx, Cx,
        (long long)Nx * Cx, (long long)Cx * Nx);
    transpose_split16<<<dim3(Cx / 64, Nx / 64, Bx), 256, 0, g_s1>>>(value, valTH, valTL, Nx, Cx,
        (long long)Nx * Cx, (long long)Cx * Nx);
    // downsample (3-term, fp16 hi/lo plane out)
    gemm_mma<1, 1><<<dim3(Cx / 128, 1, Bx), 256, GSMEM, g_s1>>>(
        kdsH, kdsL, keyTH, keyTL, nullptr, nullptr, kdH, kdL,
        Kx, Cx, Nx, 0, (long long)Cx * Nx, (long long)Kx * Cx);
    gemm_mma<1, 1><<<dim3(Cx / 128, 1, Bx), 256, GSMEM, g_s1>>>(
        vdsH, vdsL, valTH, valTL, nullptr, nullptr, vdH, vdL,
        Kx, Cx, Nx, 0, (long long)Cx * Nx, (long long)Kx * Cx);
    // k/v projections (3-term, fp32 out)
    gemm_mma<1, 0><<<dim3(Cx / 128, (Bx * Kx) / 128, 1), 256, GSMEM, g_s1>>>(
        kdH, kdL, wkTH, wkTL, bk, kk, nullptr, nullptr,
        Bx * Kx, Cx, Cx, 0, 0, 0);
    gemm_mma<1, 0><<<dim3(Cx / 128, (Bx * Kx) / 128, 1), 256, GSMEM, g_s1>>>(
        vdH, vdL, wvTH, wvTL, bv, vv, nullptr, nullptr,
        Bx * Kx, Cx, Cx, 0, 0, 0);
    cudaEventRecord(g_evB, g_s1);

    // ---- main stream: Q chain ----
    {
        long long t4 = (long long)Bx * Nx * Cx / 4;
        convert16<<<(unsigned)((t4 + 255) / 256), 256>>>(query, qH, nullptr, t4);
    }
    transpose_split16<<<dim3(Cx / 64, Cx / 64, 1), 256>>>(Wq, wqTH, wqTL, Cx, Cx, 0, 0);
    transpose_split16<<<dim3(Cx / 64, Cx / 64, 1), 256>>>(Wo, woTH, woTL, Cx, Cx, 0, 0);

    // q = query @ Wq + bq : M=65536, N=768, K=768 -> fp32 (2-term)
    gemm_mma<0, 0><<<dim3(Cx / 128, (Bx * Nx) / 128, 1), 256, GSMEM>>>(
        qH, nullptr, wqTH, wqTL, bq, q, nullptr, nullptr,
        Bx * Nx, Cx, Cx, 0, 0, 0);

    // ================= join =================
    cudaStreamWaitEvent(0, g_evB, 0);

    // chunk summaries + attention
    chunk_stats<<<Bx * Hx * 32, 64>>>(q, kk, vv,
                                      mqW, mqb, mqg, mqbe,
                                      mkW, mkb, mkg, mkbe,
                                      rfk, beta);
    attn_kernel<<<Bx * Hx * 32, 256>>>(q, kk, vv, rfk, beta, attH);

    // out = att @ Wo + bo : M=65536, N=768, K=768 -> fp32 (2-term)
    gemm_mma<0, 0><<<dim3(Cx / 128, (Bx * Nx) / 128, 1), 256, GSMEM>>>(
        attH, nullptr, woTH, woTL, bo, out, nullptr, nullptr,
        Bx * Nx, Cx, Cx, 0, 0, 0);
}

// round 11
// speedup vs baseline: 1.2327x; 1.2131x over previous
#include <cuda_runtime.h>
#include <cuda_fp16.h>
#include <math.h>
#include <stdint.h>

// Problem constants
#define Bx   64
#define Nx   1024
#define Cx   768
#define Hx   12
#define DHx  64
#define Kx   64
#define SCALEx 0.125f
#define LN_EPSx 1e-6f

// ------------------------- device scratch -------------------------
__device__ float g_q   [(long long)Bx * Nx * Cx];
__device__ float g_k   [(long long)Bx * Kx * Cx];
__device__ float g_v   [(long long)Bx * Kx * Cx];
__device__ float g_rfk [(long long)Bx * Hx * 32 * DHx];
__device__ float g_beta[(long long)Bx * Hx * 32 * DHx];

// fp16 planes (row-major)
__device__ __half g_qH   [(long long)Bx * Nx * Cx];
__device__ __half g_attH [(long long)Bx * Nx * Cx];
__device__ __half g_kdsH [Kx * Nx];
__device__ __half g_kdsL [Kx * Nx];
__device__ __half g_vdsH [Kx * Nx];
__device__ __half g_vdsL [Kx * Nx];
__device__ __half g_keyTH[(long long)Bx * Cx * Nx];
__device__ __half g_keyTL[(long long)Bx * Cx * Nx];
__device__ __half g_valTH[(long long)Bx * Cx * Nx];
__device__ __half g_valTL[(long long)Bx * Cx * Nx];
__device__ __half g_kdH  [(long long)Bx * Kx * Cx];
__device__ __half g_kdL  [(long long)Bx * Kx * Cx];
__device__ __half g_vdH  [(long long)Bx * Kx * Cx];
__device__ __half g_vdL  [(long long)Bx * Kx * Cx];
__device__ __half g_wqTH [Cx * Cx];
__device__ __half g_wqTL [Cx * Cx];
__device__ __half g_wkTH [Cx * Cx];
__device__ __half g_wkTL [Cx * Cx];
__device__ __half g_wvTH [Cx * Cx];
__device__ __half g_wvTL [Cx * Cx];
__device__ __half g_woTH [Cx * Cx];
__device__ __half g_woTL [Cx * Cx];

// ------------------------- helpers -------------------------
__device__ __forceinline__ uint32_t smem_u32(const void* p) {
    uint32_t a;
    asm("{ .reg .u64 t; cvta.to.shared.u64 t, %1; cvt.u32.u64 %0, t; }" : "=r"(a) : "l"(p));
    return a;
}
__device__ __forceinline__ void cp16(uint32_t dst, const void* src, int srcsz) {
    asm volatile("cp.async.cg.shared.global [%0], [%1], 16, %2;"
                 :: "r"(dst), "l"(src), "r"(srcsz) : "memory");
}
#define CP_COMMIT() asm volatile("cp.async.commit_group;" ::: "memory")
#define CP_WAIT1()  asm volatile("cp.async.wait_group 1;" ::: "memory")
#define CP_WAIT0()  asm volatile("cp.async.wait_group 0;" ::: "memory")

__device__ __forceinline__ void ldm_x4(uint32_t* r, uint32_t a) {
    asm volatile("ldmatrix.sync.aligned.m8n8.x4.shared.b16 {%0,%1,%2,%3}, [%4];"
                 : "=r"(r[0]), "=r"(r[1]), "=r"(r[2]), "=r"(r[3]) : "r"(a));
}
__device__ __forceinline__ void mma_f16(float* d, const uint32_t* a, const uint32_t* b) {
    asm volatile("mma.sync.aligned.m16n8k16.row.col.f32.f16.f16.f32 "
                 "{%0,%1,%2,%3},{%4,%5,%6,%7},{%8,%9},{%0,%1,%2,%3};"
                 : "+f"(d[0]), "+f"(d[1]), "+f"(d[2]), "+f"(d[3])
                 : "r"(a[0]), "r"(a[1]), "r"(a[2]), "r"(a[3]), "r"(b[0]), "r"(b[1]));
}

// ------------------------- convert (row-major, hi [+lo]) -------------------------
__global__ __launch_bounds__(256)
void convert16(const float* __restrict__ in,
               __half* __restrict__ oh, __half* __restrict__ ol,
               long long total4)
{
    const long long g = (long long)blockIdx.x * 256 + threadIdx.x;
    if (g >= total4) return;
    float4 f = ((const float4*)in)[g];
    __half h[4];
    h[0] = __float2half(f.x); h[1] = __float2half(f.y);
    h[2] = __float2half(f.z); h[3] = __float2half(f.w);
    *(uint2*)(oh + g * 4) = *(uint2*)h;
    if (ol) {
        __half l[4];
        l[0] = __float2half(f.x - __half2float(h[0]));
        l[1] = __float2half(f.y - __half2float(h[1]));
        l[2] = __float2half(f.z - __half2float(h[2]));
        l[3] = __float2half(f.w - __half2float(h[3]));
        *(uint2*)(ol + g * 4) = *(uint2*)l;
    }
}

// ------------------------- transpose + split ------------
__global__ __launch_bounds__(256)
void transpose_split16(const float* __restrict__ in,
                       __half* __restrict__ oh, __half* __restrict__ ol,
                       int R, int Cc, long long sIn, long long sOut)
{
    __shared__ float t[64][65];
    in += (long long)blockIdx.z * sIn;
    oh += (long long)blockIdx.z * sOut;
    ol += (long long)blockIdx.z * sOut;
    const int r0 = blockIdx.y * 64;
    const int c0 = blockIdx.x * 64;
    const int tid = threadIdx.x;
    #pragma unroll
    for (int it = 0; it < 4; it++) {
        const int idx = it * 256 + tid;
        const int row = idx >> 4;
        const int c4  = (idx & 15) * 4;
        float4 f = *(const float4*)(in + (long long)(r0 + row) * Cc + c0 + c4);
        t[row][c4 + 0] = f.x; t[row][c4 + 1] = f.y;
        t[row][c4 + 2] = f.z; t[row][c4 + 3] = f.w;
    }
    __syncthreads();
    #pragma unroll
    for (int it = 0; it < 2; it++) {
        const int idx = it * 256 + tid;
        const int oc = idx >> 3;
        const int k8 = (idx & 7) * 8;
        __half h[8], l[8];
        #pragma unroll
        for (int j = 0; j < 8; j++) {
            const float f = t[k8 + j][oc];
            h[j] = __float2half(f);
            l[j] = __float2half(f - __half2float(h[j]));
        }
        const long long base = (long long)(c0 + oc) * R + r0 + k8;
        *(uint4*)(oh + base) = *(uint4*)h;
        *(uint4*)(ol + base) = *(uint4*)l;
    }
}

// ------------------------- mma.sync GEMM (split fp16, ldmatrix) -------------------
// TERMS=1: ah*bh. TERMS=2: ah*bh + ah*bl. TERMS=3: + al*bh.
// MODE 0: fp32 out (+bias); MODE 1: fp16 hi/lo plane out.
#define TSB 80
#define PLB 10240
#define BUFB 40960
#define GSMEM (2 * BUFB)

template<int TERMS, int MODE>
__global__ __launch_bounds__(256)
void gemm_mma(const __half* __restrict__ Ah, const __half* __restrict__ Al,
              const __half* __restrict__ Bh, const __half* __restrict__ Bl,
              const float* __restrict__ bias,
              float* __restrict__ Cf,
              __half* __restrict__ Ch, __half* __restrict__ Cl,
              int M, int Nn, int Kk,
              long long sA, long long sB, long long sC)
{
    extern __shared__ char sm[];
    const long long z = blockIdx.z;
    Ah += z * sA;
    if (TERMS == 3) Al += z * sA;
    Bh += z * sB;
    if (TERMS >= 2) Bl += z * sB;

    const int bRow = blockIdx.y * 128;
    const int bCol = blockIdx.x * 128;
    const int tid  = threadIdx.x;
    const int lane = tid & 31;
    const int wid  = tid >> 5;
    const int warpRow = (wid & 3) * 32;
    const int warpCol = (wid >> 2) * 64;
    const uint32_t sb = smem_u32(sm);

    float acc[2][8][4];
    #pragma unroll
    for (int i = 0; i < 2; i++)
        #pragma unroll
        for (int j = 0; j < 8; j++)
            #pragma unroll
            for (int r = 0; r < 4; r++) acc[i][j][r] = 0.f;

    const int nCh = Kk / 32;

    auto loadChunk = [&](int c, int buf) {
        const int k0 = c * 32;
        const uint32_t d = sb + buf * BUFB;
        #pragma unroll
        for (int s2 = 0; s2 < 2; s2++) {
            const int row = s2 * 64 + (tid >> 2);
            const int g   = tid & 3;
            const uint32_t doff = row * TSB + g * 16;
            const int ar = bRow + row;
            const int sz = (ar < M) ? 16 : 0;
            const long long aoff = (long long)((ar < M) ? ar : 0) * Kk + k0 + g * 8;
            cp16(d + doff, Ah + aoff, sz);
            if (TERMS == 3) cp16(d + PLB + doff, Al + aoff, sz);
            const long long boff = (long long)(bCol + row) * Kk + k0 + g * 8;
            cp16(d + 2 * PLB + doff, Bh + boff, 16);
            if (TERMS >= 2) cp16(d + 3 * PLB + doff, Bl + boff, 16);
        }
        CP_COMMIT();
    };

    const int aRowSel = (lane & 15);
    const int aKHalf  = (lane >> 4) & 1;
    const int bRowSel = (lane & 7) + ((lane >> 4) & 1) * 8;
    const int bKHalf  = (lane >> 3) & 1;

    loadChunk(0, 0);
    for (int c = 0; c < nCh; c++) {
        const int buf = c & 1;
        if (c + 1 < nCh) { loadChunk(c + 1, buf ^ 1); CP_WAIT1(); }
        else             { CP_WAIT0(); }
        __syncthreads();

        const uint32_t aT = sb + buf * BUFB;
        const uint32_t bT = aT + 2 * PLB;

        #pragma unroll
        for (int s = 0; s < 2; s++) {
            const int kb = s * 32;
            uint32_t ah[2][4], al[2][4];
            #pragma unroll
            for (int i = 0; i < 2; i++) {
                const uint32_t ad = aT + (warpRow + i * 16 + aRowSel) * TSB
                                       + kb + aKHalf * 16;
                ldm_x4(ah[i], ad);
                if (TERMS == 3) ldm_x4(al[i], ad + PLB);
            }
            #pragma unroll
            for (int jp = 0; jp < 4; jp++) {
                const uint32_t bd = bT + (warpCol + jp * 16 + bRowSel) * TSB
                                       + kb + bKHalf * 16;
                uint32_t bh[4], bl2[4];
                ldm_x4(bh, bd);
                if (TERMS >= 2) ldm_x4(bl2, bd + PLB);
                #pragma unroll
                for (int jj = 0; jj < 2; jj++) {
                    #pragma unroll
                    for (int i = 0; i < 2; i++) {
                        float* dacc = acc[i][2 * jp + jj];
                        mma_f16(dacc, ah[i], &bh[2 * jj]);
                        if (TERMS >= 2) mma_f16(dacc, ah[i], &bl2[2 * jj]);
                        if (TERMS == 3) mma_f16(dacc, al[i], &bh[2 * jj]);
                    }
                }
            }
        }
        __syncthreads();
    }

    // ------------- epilogue -------------
    const int rB = bRow + warpRow + (lane >> 2);
    if (MODE == 0) {
        float* C = Cf + z * sC;
        #pragma unroll
        for (int i = 0; i < 2; i++) {
            #pragma unroll
            for (int j = 0; j < 8; j++) {
                const int col = bCol + warpCol + j * 8 + (lane & 3) * 2;
                float bx = 0.f, by = 0.f;
                if (bias) { bx = bias[col]; by = bias[col + 1]; }
                const int r = rB + i * 16;
                if (r < M) {
                    float2 o = make_float2(acc[i][j][0] + bx, acc[i][j][1] + by);
                    *(float2*)(C + (long long)r * Nn + col) = o;
                }
                if (r + 8 < M) {
                    float2 o = make_float2(acc[i][j][2] + bx, acc[i][j][3] + by);
                    *(float2*)(C + (long long)(r + 8) * Nn + col) = o;
                }
            }
        }
    } else {
        __half* CH = Ch + z * sC;
        __half* CL = Cl + z * sC;
        #pragma unroll
        for (int i = 0; i < 2; i++) {
            #pragma unroll
            for (int j = 0; j < 8; j++) {
                const int col = bCol + warpCol + j * 8 + (lane & 3) * 2;
                #pragma unroll
                for (int half = 0; half < 2; half++) {
                    const int r = rB + i * 16 + half * 8;
                    if (r >= M) continue;
                    const float v0 = acc[i][j][2 * half + 0];
                    const float v1 = acc[i][j][2 * half + 1];
                    __half h0 = __float2half(v0);
                    __half h1 = __float2half(v1);
                    __half l0 = __float2half(v0 - __half2float(h0));
                    __half l1 = __float2half(v1 - __half2float(h1));
                    __half hp[2] = {h0, h1}, lp[2] = {l0, l1};
                    const long long base = (long long)r * Nn + col;
                    *(uint32_t*)(CH + base) = *(uint32_t*)hp;
                    *(uint32_t*)(CL + base) = *(uint32_t*)lp;
                }
            }
        }
    }
}

// ------------------------- chunk stats -------------------------
__device__ __forceinline__ float blk_reduce64(float x, float* red)
{
    const int d = threadIdx.x;
    #pragma unroll
    for (int o = 16; o > 0; o >>= 1)
        x += __shfl_down_sync(0xffffffffu, x, o);
    if ((d & 31) == 0) red[d >> 5] = x;
    __syncthreads();
    const float r = red[0] + red[1];
    __syncthreads();
    return r;
}

__global__ __launch_bounds__(64)
void chunk_stats(const float* __restrict__ q, const float* __restrict__ k,
                 const float* __restrict__ v,
                 const float* __restrict__ mqW, const float* __restrict__ mqb,
                 const float* __restrict__ mqg, const float* __restrict__ mqbe,
                 const float* __restrict__ mkW, const float* __restrict__ mkb,
                 const float* __restrict__ mkg, const float* __restrict__ mkbe,
                 float* __restrict__ rfk, float* __restrict__ beta)
{
    const int blk = blockIdx.x;
    const int c  = blk & 31;
    const int bh = blk >> 5;
    const int h  = bh % Hx;
    const int b  = bh / Hx;
    const int d  = threadIdx.x;

    __shared__ float qm[64], km[64], k0s[64], k1s[64], v0s[64], v1s[64];
    __shared__ float red[2];
    __shared__ float probs[2];

    {
        const float* qb = q + ((long long)(b * Nx + c * 32)) * Cx + h * DHx + d;
        float s = 0.f;
        #pragma unroll 8
        for (int i = 0; i < 32; i++) s += qb[(long long)i * Cx];
        qm[d] = s * (1.f / 32.f);
    }
    {
        const float* kb = k + ((long long)(b * Kx + c * 2)) * Cx + h * DHx + d;
        const float k0v = kb[0], k1v = kb[Cx];
        k0s[d] = k0v; k1s[d] = k1v;
        km[d]  = 0.5f * (k0v + k1v);
        const float* vb = v + ((long long)(b * Kx + c * 2)) * Cx + h * DHx + d;
        v0s[d] = vb[0]; v1s[d] = vb[Cx];
    }
    __syncthreads();

    float yq = mqb[d], yk = mkb[d];
    #pragma unroll 8
    for (int e = 0; e < 64; e++) {
        yq = fmaf(qm[e], mqW[e * 64 + d], yq);
        yk = fmaf(km[e], mkW[e * 64 + d], yk);
    }

    float m  = blk_reduce64(yq, red) * (1.f / 64.f);
    float dv = yq - m;
    float var = blk_reduce64(dv * dv, red) * (1.f / 64.f);
    const float qbar = dv * rsqrtf(var + LN_EPSx) * mqg[d] + mqbe[d];

    m  = blk_reduce64(yk, red) * (1.f / 64.f);
    dv = yk - m;
    var = blk_reduce64(dv * dv, red) * (1.f / 64.f);
    const float kbar = dv * rsqrtf(var + LN_EPSx) * mkg[d] + mkbe[d];

    rfk[((long long)bh * 32 + c) * 64 + d] = kbar;

    const float mu = 0.5f * (qbar + kbar);

    const float s0 = blk_reduce64(mu * k0s[d], red);
    const float n0 = blk_reduce64(k0s[d] * k0s[d], red);
    const float s1 = blk_reduce64(mu * k1s[d], red);
    const float n1 = blk_reduce64(k1s[d] * k1s[d], red);

    if (d == 0) {
        const float dn = 0.125f;
        const float l0 = dn * s0 - 0.5f * dn * n0;
        const float l1 = dn * s1 - 0.5f * dn * n1;
        const float mx = fmaxf(l0, l1);
        const float e0 = expf(l0 - mx);
        const float e1 = expf(l1 - mx);
        const float inv = 1.f / (e0 + e1);
        probs[0] = e0 * inv;
        probs[1] = e1 * inv;
    }
    __syncthreads();

    beta[((long long)bh * 32 + c) * 64 + d] = probs[0] * v0s[d] + probs[1] * v1s[d];
}

// ------------------------- attention (fp16 hi output) -------------------------
__global__ __launch_bounds__(256)
void attn_kernel(const float* __restrict__ q, const float* __restrict__ k,
                 const float* __restrict__ v,
                 const float* __restrict__ rfk, const float* __restrict__ betag,
                 __half* __restrict__ outH)
{
    const int blk = blockIdx.x;
    const int w  = blk & 31;
    const int bh = blk >> 5;
    const int h  = bh % Hx;
    const int b  = bh / Hx;

    __shared__ float qs [32][65];
    __shared__ float kbs[32][64];
    __shared__ float bes[32][64];
    __shared__ float wks[2][64];
    __shared__ float wvs[2][64];
    __shared__ float lg [32][35];

    const int t = threadIdx.x;

    for (int idx = t; idx < 2048; idx += 256) {
        const int i = idx >> 6, d = idx & 63;
        qs [i][d] = q    [((long long)(b * Nx + w * 32 + i)) * Cx + h * DHx + d];
        kbs[i][d] = rfk  [((long long)bh * 32 + i) * 64 + d];
        bes[i][d] = betag[((long long)bh * 32 + i) * 64 + d];
    }
    if (t < 128) {
        const int j = t >> 6, d = t & 63;
        wks[j][d] = k[((long long)(b * Kx + w * 2 + j)) * Cx + h * DHx + d];
        wvs[j][d] = v[((long long)(b * Kx + w * 2 + j)) * Cx + h * DHx + d];
    }
    __syncthreads();

    {
        const int i   = t & 31;
        const int sl0 = t >> 5;
        for (int slot = sl0; slot < 34; slot += 8) {
            const float* kv = (slot < 2) ? &wks[slot][0] : &kbs[slot - 2][0];
            float s = 0.f;
            #pragma unroll
            for (int e = 0; e < 64; e++) s = fmaf(qs[i][e], kv[e], s);
            lg[i][slot] = s * SCALEx;
        }
    }
    __syncthreads();

    if (t < 32) {
        float mx = -1e30f;
        #pragma unroll
        for (int s = 0; s < 34; s++) mx = fmaxf(mx, lg[t][s]);
        float sum = 0.f;
        #pragma unroll
        for (int s = 0; s < 34; s++) { const float e = expf(lg[t][s] - mx); lg[t][s] = e; sum += e; }
        const float inv = 1.f / sum;
        #pragma unroll
        for (int s = 0; s < 34; s++) lg[t][s] *= inv;
    }
    __syncthreads();

    const int d = t & 63;
    #pragma unroll
    for (int p = 0; p < 8; p++) {
        const int ii = p * 4 + (t >> 6);
        float acc = lg[ii][0] * wvs[0][d] + lg[ii][1] * wvs[1][d];
        #pragma unroll
        for (int c2 = 0; c2 < 32; c2++)
            acc = fmaf(lg[ii][2 + c2], bes[c2][d], acc);
        const long long ro = ((long long)(b * Nx + w * 32 + ii)) * Cx + h * DHx + d;
        outH[ro] = __float2half(acc);
    }
}

// ------------------------- launch -------------------------
static cudaStream_t g_s1 = nullptr;
static cudaEvent_t  g_evA = nullptr, g_evB = nullptr;

extern "C" void kernel_launch(void* const* d_in, const int* in_sizes, int n_in,
                              void* d_out, int out_size)
{
    const float* query = (const float*)d_in[0];
    const float* key   = (const float*)d_in[1];
    const float* value = (const float*)d_in[2];
    const float* Wq    = (const float*)d_in[3];
    const float* bq    = (const float*)d_in[4];
    const float* Wk    = (const float*)d_in[5];
    const float* bk    = (const float*)d_in[6];
    const float* Wv    = (const float*)d_in[7];
    const float* bv    = (const float*)d_in[8];
    const float* Wo    = (const float*)d_in[9];
    const float* bo    = (const float*)d_in[10];
    const float* kds   = (const float*)d_in[11];
    const float* vds   = (const float*)d_in[12];
    const float* mqW   = (const float*)d_in[13];
    const float* mqb   = (const float*)d_in[14];
    const float* mqg   = (const float*)d_in[15];
    const float* mqbe  = (const float*)d_in[16];
    const float* mkW   = (const float*)d_in[17];
    const float* mkb   = (const float*)d_in[18];
    const float* mkg   = (const float*)d_in[19];
    const float* mkbe  = (const float*)d_in[20];
    float* out = (float*)d_out;

    if (!g_s1) {
        cudaStreamCreateWithFlags(&g_s1, cudaStreamNonBlocking);
        cudaEventCreateWithFlags(&g_evA, cudaEventDisableTiming);
        cudaEventCreateWithFlags(&g_evB, cudaEventDisableTiming);
    }

    float *q, *kk, *vv, *rfk, *beta;
    cudaGetSymbolAddress((void**)&q,    g_q);
    cudaGetSymbolAddress((void**)&kk,   g_k);
    cudaGetSymbolAddress((void**)&vv,   g_v);
    cudaGetSymbolAddress((void**)&rfk,  g_rfk);
    cudaGetSymbolAddress((void**)&beta, g_beta);

    __half *qH, *attH, *kdsH, *kdsL, *vdsH, *vdsL;
    __half *keyTH, *keyTL, *valTH, *valTL, *kdH, *kdL, *vdH, *vdL;
    __half *wqTH, *wqTL, *wkTH, *wkTL, *wvTH, *wvTL, *woTH, *woTL;
    cudaGetSymbolAddress((void**)&qH,    g_qH);
    cudaGetSymbolAddress((void**)&attH,  g_attH);
    cudaGetSymbolAddress((void**)&kdsH,  g_kdsH);
    cudaGetSymbolAddress((void**)&kdsL,  g_kdsL);
    cudaGetSymbolAddress((void**)&vdsH,  g_vdsH);
    cudaGetSymbolAddress((void**)&vdsL,  g_vdsL);
    cudaGetSymbolAddress((void**)&keyTH, g_keyTH);
    cudaGetSymbolAddress((void**)&keyTL, g_keyTL);
    cudaGetSymbolAddress((void**)&valTH, g_valTH);
    cudaGetSymbolAddress((void**)&valTL, g_valTL);
    cudaGetSymbolAddress((void**)&kdH,   g_kdH);
    cudaGetSymbolAddress((void**)&kdL,   g_kdL);
    cudaGetSymbolAddress((void**)&vdH,   g_vdH);
    cudaGetSymbolAddress((void**)&vdL,   g_vdL);
    cudaGetSymbolAddress((void**)&wqTH,  g_wqTH);
    cudaGetSymbolAddress((void**)&wqTL,  g_wqTL);
    cudaGetSymbolAddress((void**)&wkTH,  g_wkTH);
    cudaGetSymbolAddress((void**)&wkTL,  g_wkTL);
    cudaGetSymbolAddress((void**)&wvTH,  g_wvTH);
    cudaGetSymbolAddress((void**)&wvTL,  g_wvTL);
    cudaGetSymbolAddress((void**)&woTH,  g_woTH);
    cudaGetSymbolAddress((void**)&woTL,  g_woTL);

    cudaFuncSetAttribute(gemm_mma<1, 0>, cudaFuncAttributeMaxDynamicSharedMemorySize, GSMEM);
    cudaFuncSetAttribute(gemm_mma<3, 0>, cudaFuncAttributeMaxDynamicSharedMemorySize, GSMEM);
    cudaFuncSetAttribute(gemm_mma<3, 1>, cudaFuncAttributeMaxDynamicSharedMemorySize, GSMEM);

    // ================= fork: side stream handles the KV chain =================
    cudaEventRecord(g_evA, 0);
    cudaStreamWaitEvent(g_s1, g_evA, 0);

    // ---- side stream (g_s1): KV chain ----
    {
        long long t4 = (long long)Kx * Nx / 4;
        convert16<<<(unsigned)((t4 + 255) / 256), 256, 0, g_s1>>>(kds, kdsH, kdsL, t4);
        convert16<<<(unsigned)((t4 + 255) / 256), 256, 0, g_s1>>>(vds, vdsH, vdsL, t4);
    }
    transpose_split16<<<dim3(Cx / 64, Cx / 64, 1), 256, 0, g_s1>>>(Wk, wkTH, wkTL, Cx, Cx, 0, 0);
    transpose_split16<<<dim3(Cx / 64, Cx / 64, 1), 256, 0, g_s1>>>(Wv, wvTH, wvTL, Cx, Cx, 0, 0);
    transpose_split16<<<dim3(Cx / 64, Nx / 64, Bx), 256, 0, g_s1>>>(key, keyTH, keyTL, Nx, Cx,
        (long long)Nx * Cx, (long long)Cx * Nx);
    transpose_split16<<<dim3(Cx / 64, Nx / 64, Bx), 256, 0, g_s1>>>(value, valTH, valTL, Nx, Cx,
        (long long)Nx * Cx, (long long)Cx * Nx);
    // downsample (3-term, fp16 hi/lo plane out)
    gemm_mma<3, 1><<<dim3(Cx / 128, 1, Bx), 256, GSMEM, g_s1>>>(
        kdsH, kdsL, keyTH, keyTL, nullptr, nullptr, kdH, kdL,
        Kx, Cx, Nx, 0, (long long)Cx * Nx, (long long)Kx * Cx);
    gemm_mma<3, 1><<<dim3(Cx / 128, 1, Bx), 256, GSMEM, g_s1>>>(
        vdsH, vdsL, valTH, valTL, nullptr, nullptr, vdH, vdL,
        Kx, Cx, Nx, 0, (long long)Cx * Nx, (long long)Kx * Cx);
    // k/v projections (3-term, fp32 out)
    gemm_mma<3, 0><<<dim3(Cx / 128, (Bx * Kx) / 128, 1), 256, GSMEM, g_s1>>>(
        kdH, kdL, wkTH, wkTL, bk, kk, nullptr, nullptr,
        Bx * Kx, Cx, Cx, 0, 0, 0);
    gemm_mma<3, 0><<<dim3(Cx / 128, (Bx * Kx) / 128, 1), 256, GSMEM, g_s1>>>(
        vdH, vdL, wvTH, wvTL, bv, vv, nullptr, nullptr,
        Bx * Kx, Cx, Cx, 0, 0, 0);
    cudaEventRecord(g_evB, g_s1);

    // ---- main stream: Q chain ----
    {
        long long t4 = (long long)Bx * Nx * Cx / 4;
        convert16<<<(unsigned)((t4 + 255) / 256), 256>>>(query, qH, nullptr, t4);
    }
    transpose_split16<<<dim3(Cx / 64, Cx / 64, 1), 256>>>(Wq, wqTH, wqTL, Cx, Cx, 0, 0);
    transpose_split16<<<dim3(Cx / 64, Cx / 64, 1), 256>>>(Wo, woTH, woTL, Cx, Cx, 0, 0);

    // q = query @ Wq + bq : M=65536, N=768, K=768 -> fp32 (1-term pure fp16)
    gemm_mma<1, 0><<<dim3(Cx / 128, (Bx * Nx) / 128, 1), 256, GSMEM>>>(
        qH, nullptr, wqTH, wqTL, bq, q, nullptr, nullptr,
        Bx * Nx, Cx, Cx, 0, 0, 0);

    // ================= join =================
    cudaStreamWaitEvent(0, g_evB, 0);

    // chunk summaries + attention
    chunk_stats<<<Bx * Hx * 32, 64>>>(q, kk, vv,
                                      mqW, mqb, mqg, mqbe,
                                      mkW, mkb, mkg, mkbe,
                                      rfk, beta);
    attn_kernel<<<Bx * Hx * 32, 256>>>(q, kk, vv, rfk, beta, attH);

    // out = att @ Wo + bo : M=65536, N=768, K=768 -> fp32 (1-term pure fp16)
    gemm_mma<1, 0><<<dim3(Cx / 128, (Bx * Nx) / 128, 1), 256, GSMEM>>>(
        attH, nullptr, woTH, woTL, bo, out, nullptr, nullptr,
        Bx * Nx, Cx, Cx, 0, 0, 0);
}

// round 12
// speedup vs baseline: 1.3569x; 1.1008x over previous
#include <cuda_runtime.h>
#include <cuda_fp16.h>
#include <math.h>
#include <stdint.h>

// Problem constants
#define Bx   64
#define Nx   1024
#define Cx   768
#define Hx   12
#define DHx  64
#define Kx   64
#define SCALEx 0.125f
#define LN_EPSx 1e-6f

// ------------------------- device scratch -------------------------
__device__ float g_q   [(long long)Bx * Nx * Cx];
__device__ float g_k   [(long long)Bx * Kx * Cx];
__device__ float g_v   [(long long)Bx * Kx * Cx];
__device__ float g_rfk [(long long)Bx * Hx * 32 * DHx];
__device__ float g_beta[(long long)Bx * Hx * 32 * DHx];

// fp16 planes (row-major)
__device__ __half g_qH   [(long long)Bx * Nx * Cx];
__device__ __half g_attH [(long long)Bx * Nx * Cx];
__device__ __half g_kdsH [Kx * Nx];
__device__ __half g_kdsL [Kx * Nx];
__device__ __half g_vdsH [Kx * Nx];
__device__ __half g_vdsL [Kx * Nx];
__device__ __half g_keyTH[(long long)Bx * Cx * Nx];
__device__ __half g_valTH[(long long)Bx * Cx * Nx];
__device__ __half g_kdH  [(long long)Bx * Kx * Cx];
__device__ __half g_kdL  [(long long)Bx * Kx * Cx];
__device__ __half g_vdH  [(long long)Bx * Kx * Cx];
__device__ __half g_vdL  [(long long)Bx * Kx * Cx];
__device__ __half g_wqTH [Cx * Cx];
__device__ __half g_wkTH [Cx * Cx];
__device__ __half g_wvTH [Cx * Cx];
__device__ __half g_woTH [Cx * Cx];

// ------------------------- helpers -------------------------
__device__ __forceinline__ uint32_t smem_u32(const void* p) {
    uint32_t a;
    asm("{ .reg .u64 t; cvta.to.shared.u64 t, %1; cvt.u32.u64 %0, t; }" : "=r"(a) : "l"(p));
    return a;
}
__device__ __forceinline__ void cp16(uint32_t dst, const void* src, int srcsz) {
    asm volatile("cp.async.cg.shared.global [%0], [%1], 16, %2;"
                 :: "r"(dst), "l"(src), "r"(srcsz) : "memory");
}
#define CP_COMMIT() asm volatile("cp.async.commit_group;" ::: "memory")
#define CP_WAIT1()  asm volatile("cp.async.wait_group 1;" ::: "memory")
#define CP_WAIT0()  asm volatile("cp.async.wait_group 0;" ::: "memory")

__device__ __forceinline__ void ldm_x4(uint32_t* r, uint32_t a) {
    asm volatile("ldmatrix.sync.aligned.m8n8.x4.shared.b16 {%0,%1,%2,%3}, [%4];"
                 : "=r"(r[0]), "=r"(r[1]), "=r"(r[2]), "=r"(r[3]) : "r"(a));
}
__device__ __forceinline__ void mma_f16(float* d, const uint32_t* a, const uint32_t* b) {
    asm volatile("mma.sync.aligned.m16n8k16.row.col.f32.f16.f16.f32 "
                 "{%0,%1,%2,%3},{%4,%5,%6,%7},{%8,%9},{%0,%1,%2,%3};"
                 : "+f"(d[0]), "+f"(d[1]), "+f"(d[2]), "+f"(d[3])
                 : "r"(a[0]), "r"(a[1]), "r"(a[2]), "r"(a[3]), "r"(b[0]), "r"(b[1]));
}

// ------------------------- convert (row-major, hi [+lo]) -------------------------
__global__ __launch_bounds__(256)
void convert16(const float* __restrict__ in,
               __half* __restrict__ oh, __half* __restrict__ ol,
               long long total4)
{
    const long long g = (long long)blockIdx.x * 256 + threadIdx.x;
    if (g >= total4) return;
    float4 f = ((const float4*)in)[g];
    __half h[4];
    h[0] = __float2half(f.x); h[1] = __float2half(f.y);
    h[2] = __float2half(f.z); h[3] = __float2half(f.w);
    *(uint2*)(oh + g * 4) = *(uint2*)h;
    if (ol) {
        __half l[4];
        l[0] = __float2half(f.x - __half2float(h[0]));
        l[1] = __float2half(f.y - __half2float(h[1]));
        l[2] = __float2half(f.z - __half2float(h[2]));
        l[3] = __float2half(f.w - __half2float(h[3]));
        *(uint2*)(ol + g * 4) = *(uint2*)l;
    }
}

// ------------------------- transpose (hi plane only) ------------
__global__ __launch_bounds__(256)
void transpose16(const float* __restrict__ in,
                 __half* __restrict__ oh,
                 int R, int Cc, long long sIn, long long sOut)
{
    __shared__ float t[64][65];
    in += (long long)blockIdx.z * sIn;
    oh += (long long)blockIdx.z * sOut;
    const int r0 = blockIdx.y * 64;
    const int c0 = blockIdx.x * 64;
    const int tid = threadIdx.x;
    #pragma unroll
    for (int it = 0; it < 4; it++) {
        const int idx = it * 256 + tid;
        const int row = idx >> 4;
        const int c4  = (idx & 15) * 4;
        float4 f = *(const float4*)(in + (long long)(r0 + row) * Cc + c0 + c4);
        t[row][c4 + 0] = f.x; t[row][c4 + 1] = f.y;
        t[row][c4 + 2] = f.z; t[row][c4 + 3] = f.w;
    }
    __syncthreads();
    #pragma unroll
    for (int it = 0; it < 2; it++) {
        const int idx = it * 256 + tid;
        const int oc = idx >> 3;
        const int k8 = (idx & 7) * 8;
        __half h[8];
        #pragma unroll
        for (int j = 0; j < 8; j++)
            h[j] = __float2half(t[k8 + j][oc]);
        const long long base = (long long)(c0 + oc) * R + r0 + k8;
        *(uint4*)(oh + base) = *(uint4*)h;
    }
}

// ------------------------- mma.sync GEMM (split fp16, ldmatrix) -------------------
// TERMS=1: ah*bh.
// TERMS=2: ah*bh + ah*bl   (B split, A hi)
// TERMS=3: ah*bh + ah*bl + al*bh
// TERMS=4: ah*bh + al*bh   (A split, B hi)
// MODE 0: fp32 out (+bias); MODE 1: fp16 hi/lo plane out.
#define TSB 80
#define PLB 10240
#define BUFB 40960
#define GSMEM (2 * BUFB)

template<int TERMS, int MODE>
__global__ __launch_bounds__(256)
void gemm_mma(const __half* __restrict__ Ah, const __half* __restrict__ Al,
              const __half* __restrict__ Bh, const __half* __restrict__ Bl,
              const float* __restrict__ bias,
              float* __restrict__ Cf,
              __half* __restrict__ Ch, __half* __restrict__ Cl,
              int M, int Nn, int Kk,
              long long sA, long long sB, long long sC)
{
    constexpr bool HAS_AL = (TERMS >= 3);
    constexpr bool HAS_BL = (TERMS == 2 || TERMS == 3);

    extern __shared__ char sm[];
    const long long z = blockIdx.z;
    Ah += z * sA;
    if (HAS_AL) Al += z * sA;
    Bh += z * sB;
    if (HAS_BL) Bl += z * sB;

    const int bRow = blockIdx.y * 128;
    const int bCol = blockIdx.x * 128;
    const int tid  = threadIdx.x;
    const int lane = tid & 31;
    const int wid  = tid >> 5;
    const int warpRow = (wid & 3) * 32;
    const int warpCol = (wid >> 2) * 64;
    const uint32_t sb = smem_u32(sm);

    float acc[2][8][4];
    #pragma unroll
    for (int i = 0; i < 2; i++)
        #pragma unroll
        for (int j = 0; j < 8; j++)
            #pragma unroll
            for (int r = 0; r < 4; r++) acc[i][j][r] = 0.f;

    const int nCh = Kk / 32;

    auto loadChunk = [&](int c, int buf) {
        const int k0 = c * 32;
        const uint32_t d = sb + buf * BUFB;
        #pragma unroll
        for (int s2 = 0; s2 < 2; s2++) {
            const int row = s2 * 64 + (tid >> 2);
            const int g   = tid & 3;
            const uint32_t doff = row * TSB + g * 16;
            const int ar = bRow + row;
            const int sz = (ar < M) ? 16 : 0;
            const long long aoff = (long long)((ar < M) ? ar : 0) * Kk + k0 + g * 8;
            cp16(d + doff, Ah + aoff, sz);
            if (HAS_AL) cp16(d + PLB + doff, Al + aoff, sz);
            const long long boff = (long long)(bCol + row) * Kk + k0 + g * 8;
            cp16(d + 2 * PLB + doff, Bh + boff, 16);
            if (HAS_BL) cp16(d + 3 * PLB + doff, Bl + boff, 16);
        }
        CP_COMMIT();
    };

    const int aRowSel = (lane & 15);
    const int aKHalf  = (lane >> 4) & 1;
    const int bRowSel = (lane & 7) + ((lane >> 4) & 1) * 8;
    const int bKHalf  = (lane >> 3) & 1;

    loadChunk(0, 0);
    for (int c = 0; c < nCh; c++) {
        const int buf = c & 1;
        if (c + 1 < nCh) { loadChunk(c + 1, buf ^ 1); CP_WAIT1(); }
        else             { CP_WAIT0(); }
        __syncthreads();

        const uint32_t aT = sb + buf * BUFB;
        const uint32_t bT = aT + 2 * PLB;

        #pragma unroll
        for (int s = 0; s < 2; s++) {
            const int kb = s * 32;
            uint32_t ah[2][4], al[2][4];
            #pragma unroll
            for (int i = 0; i < 2; i++) {
                const uint32_t ad = aT + (warpRow + i * 16 + aRowSel) * TSB
                                       + kb + aKHalf * 16;
                ldm_x4(ah[i], ad);
                if (HAS_AL) ldm_x4(al[i], ad + PLB);
            }
            #pragma unroll
            for (int jp = 0; jp < 4; jp++) {
                const uint32_t bd = bT + (warpCol + jp * 16 + bRowSel) * TSB
                                       + kb + bKHalf * 16;
                uint32_t bh[4], bl2[4];
                ldm_x4(bh, bd);
                if (HAS_BL) ldm_x4(bl2, bd + PLB);
                #pragma unroll
                for (int jj = 0; jj < 2; jj++) {
                    #pragma unroll
                    for (int i = 0; i < 2; i++) {
                        float* dacc = acc[i][2 * jp + jj];
                        mma_f16(dacc, ah[i], &bh[2 * jj]);
                        if (HAS_BL) mma_f16(dacc, ah[i], &bl2[2 * jj]);
                        if (HAS_AL) mma_f16(dacc, al[i], &bh[2 * jj]);
                    }
                }
            }
        }
        __syncthreads();
    }

    // ------------- epilogue -------------
    const int rB = bRow + warpRow + (lane >> 2);
    if (MODE == 0) {
        float* C = Cf + z * sC;
        #pragma unroll
        for (int i = 0; i < 2; i++) {
            #pragma unroll
            for (int j = 0; j < 8; j++) {
                const int col = bCol + warpCol + j * 8 + (lane & 3) * 2;
                float bx = 0.f, by = 0.f;
                if (bias) { bx = bias[col]; by = bias[col + 1]; }
                const int r = rB + i * 16;
                if (r < M) {
                    float2 o = make_float2(acc[i][j][0] + bx, acc[i][j][1] + by);
                    *(float2*)(C + (long long)r * Nn + col) = o;
                }
                if (r + 8 < M) {
                    float2 o = make_float2(acc[i][j][2] + bx, acc[i][j][3] + by);
                    *(float2*)(C + (long long)(r + 8) * Nn + col) = o;
                }
            }
        }
    } else {
        __half* CH = Ch + z * sC;
        __half* CL = Cl + z * sC;
        #pragma unroll
        for (int i = 0; i < 2; i++) {
            #pragma unroll
            for (int j = 0; j < 8; j++) {
                const int col = bCol + warpCol + j * 8 + (lane & 3) * 2;
                #pragma unroll
                for (int half = 0; half < 2; half++) {
                    const int r = rB + i * 16 + half * 8;
                    if (r >= M) continue;
                    const float v0 = acc[i][j][2 * half + 0];
                    const float v1 = acc[i][j][2 * half + 1];
                    __half h0 = __float2half(v0);
                    __half h1 = __float2half(v1);
                    __half l0 = __float2half(v0 - __half2float(h0));
                    __half l1 = __float2half(v1 - __half2float(h1));
                    __half hp[2] = {h0, h1}, lp[2] = {l0, l1};
                    const long long base = (long long)r * Nn + col;
                    *(uint32_t*)(CH + base) = *(uint32_t*)hp;
                    *(uint32_t*)(CL + base) = *(uint32_t*)lp;
                }
            }
        }
    }
}

// ------------------------- chunk stats -------------------------
__device__ __forceinline__ float blk_reduce64(float x, float* red)
{
    const int d = threadIdx.x;
    #pragma unroll
    for (int o = 16; o > 0; o >>= 1)
        x += __shfl_down_sync(0xffffffffu, x, o);
    if ((d & 31) == 0) red[d >> 5] = x;
    __syncthreads();
    const float r = red[0] + red[1];
    __syncthreads();
    return r;
}

__global__ __launch_bounds__(64)
void chunk_stats(const float* __restrict__ q, const float* __restrict__ k,
                 const float* __restrict__ v,
                 const float* __restrict__ mqW, const float* __restrict__ mqb,
                 const float* __restrict__ mqg, const float* __restrict__ mqbe,
                 const float* __restrict__ mkW, const float* __restrict__ mkb,
                 const float* __restrict__ mkg, const float* __restrict__ mkbe,
                 float* __restrict__ rfk, float* __restrict__ beta)
{
    const int blk = blockIdx.x;
    const int c  = blk & 31;
    const int bh = blk >> 5;
    const int h  = bh % Hx;
    const int b  = bh / Hx;
    const int d  = threadIdx.x;

    __shared__ float qm[64], km[64], k0s[64], k1s[64], v0s[64], v1s[64];
    __shared__ float red[2];
    __shared__ float probs[2];

    {
        const float* qb = q + ((long long)(b * Nx + c * 32)) * Cx + h * DHx + d;
        float s = 0.f;
        #pragma unroll 8
        for (int i = 0; i < 32; i++) s += qb[(long long)i * Cx];
        qm[d] = s * (1.f / 32.f);
    }
    {
        const float* kb = k + ((long long)(b * Kx + c * 2)) * Cx + h * DHx + d;
        const float k0v = kb[0], k1v = kb[Cx];
        k0s[d] = k0v; k1s[d] = k1v;
        km[d]  = 0.5f * (k0v + k1v);
        const float* vb = v + ((long long)(b * Kx + c * 2)) * Cx + h * DHx + d;
        v0s[d] = vb[0]; v1s[d] = vb[Cx];
    }
    __syncthreads();

    float yq = mqb[d], yk = mkb[d];
    #pragma unroll 8
    for (int e = 0; e < 64; e++) {
        yq = fmaf(qm[e], mqW[e * 64 + d], yq);
        yk = fmaf(km[e], mkW[e * 64 + d], yk);
    }

    float m  = blk_reduce64(yq, red) * (1.f / 64.f);
    float dv = yq - m;
    float var = blk_reduce64(dv * dv, red) * (1.f / 64.f);
    const float qbar = dv * rsqrtf(var + LN_EPSx) * mqg[d] + mqbe[d];

    m  = blk_reduce64(yk, red) * (1.f / 64.f);
    dv = yk - m;
    var = blk_reduce64(dv * dv, red) * (1.f / 64.f);
    const float kbar = dv * rsqrtf(var + LN_EPSx) * mkg[d] + mkbe[d];

    rfk[((long long)bh * 32 + c) * 64 + d] = kbar;

    const float mu = 0.5f * (qbar + kbar);

    const float s0 = blk_reduce64(mu * k0s[d], red);
    const float n0 = blk_reduce64(k0s[d] * k0s[d], red);
    const float s1 = blk_reduce64(mu * k1s[d], red);
    const float n1 = blk_reduce64(k1s[d] * k1s[d], red);

    if (d == 0) {
        const float dn = 0.125f;
        const float l0 = dn * s0 - 0.5f * dn * n0;
        const float l1 = dn * s1 - 0.5f * dn * n1;
        const float mx = fmaxf(l0, l1);
        const float e0 = expf(l0 - mx);
        const float e1 = expf(l1 - mx);
        const float inv = 1.f / (e0 + e1);
        probs[0] = e0 * inv;
        probs[1] = e1 * inv;
    }
    __syncthreads();

    beta[((long long)bh * 32 + c) * 64 + d] = probs[0] * v0s[d] + probs[1] * v1s[d];
}

// ------------------------- attention (fp16 hi output) -------------------------
__global__ __launch_bounds__(256)
void attn_kernel(const float* __restrict__ q, const float* __restrict__ k,
                 const float* __restrict__ v,
                 const float* __restrict__ rfk, const float* __restrict__ betag,
                 __half* __restrict__ outH)
{
    const int blk = blockIdx.x;
    const int w  = blk & 31;
    const int bh = blk >> 5;
    const int h  = bh % Hx;
    const int b  = bh / Hx;

    __shared__ float qs [32][65];
    __shared__ float kbs[32][64];
    __shared__ float bes[32][64];
    __shared__ float wks[2][64];
    __shared__ float wvs[2][64];
    __shared__ float lg [32][35];

    const int t = threadIdx.x;

    for (int idx = t; idx < 2048; idx += 256) {
        const int i = idx >> 6, d = idx & 63;
        qs [i][d] = q    [((long long)(b * Nx + w * 32 + i)) * Cx + h * DHx + d];
        kbs[i][d] = rfk  [((long long)bh * 32 + i) * 64 + d];
        bes[i][d] = betag[((long long)bh * 32 + i) * 64 + d];
    }
    if (t < 128) {
        const int j = t >> 6, d = t & 63;
        wks[j][d] = k[((long long)(b * Kx + w * 2 + j)) * Cx + h * DHx + d];
        wvs[j][d] = v[((long long)(b * Kx + w * 2 + j)) * Cx + h * DHx + d];
    }
    __syncthreads();

    {
        const int i   = t & 31;
        const int sl0 = t >> 5;
        for (int slot = sl0; slot < 34; slot += 8) {
            const float* kv = (slot < 2) ? &wks[slot][0] : &kbs[slot - 2][0];
            float s = 0.f;
            #pragma unroll
            for (int e = 0; e < 64; e++) s = fmaf(qs[i][e], kv[e], s);
            lg[i][slot] = s * SCALEx;
        }
    }
    __syncthreads();

    if (t < 32) {
        float mx = -1e30f;
        #pragma unroll
        for (int s = 0; s < 34; s++) mx = fmaxf(mx, lg[t][s]);
        float sum = 0.f;
        #pragma unroll
        for (int s = 0; s < 34; s++) { const float e = expf(lg[t][s] - mx); lg[t][s] = e; sum += e; }
        const float inv = 1.f / sum;
        #pragma unroll
        for (int s = 0; s < 34; s++) lg[t][s] *= inv;
    }
    __syncthreads();

    const int d = t & 63;
    #pragma unroll
    for (int p = 0; p < 8; p++) {
        const int ii = p * 4 + (t >> 6);
        float acc = lg[ii][0] * wvs[0][d] + lg[ii][1] * wvs[1][d];
        #pragma unroll
        for (int c2 = 0; c2 < 32; c2++)
            acc = fmaf(lg[ii][2 + c2], bes[c2][d], acc);
        const long long ro = ((long long)(b * Nx + w * 32 + ii)) * Cx + h * DHx + d;
        outH[ro] = __float2half(acc);
    }
}

// ------------------------- launch -------------------------
static cudaStream_t g_s1 = nullptr;
static cudaEvent_t  g_evA = nullptr, g_evB = nullptr;

extern "C" void kernel_launch(void* const* d_in, const int* in_sizes, int n_in,
                              void* d_out, int out_size)
{
    const float* query = (const float*)d_in[0];
    const float* key   = (const float*)d_in[1];
    const float* value = (const float*)d_in[2];
    const float* Wq    = (const float*)d_in[3];
    const float* bq    = (const float*)d_in[4];
    const float* Wk    = (const float*)d_in[5];
    const float* bk    = (const float*)d_in[6];
    const float* Wv    = (const float*)d_in[7];
    const float* bv    = (const float*)d_in[8];
    const float* Wo    = (const float*)d_in[9];
    const float* bo    = (const float*)d_in[10];
    const float* kds   = (const float*)d_in[11];
    const float* vds   = (const float*)d_in[12];
    const float* mqW   = (const float*)d_in[13];
    const float* mqb   = (const float*)d_in[14];
    const float* mqg   = (const float*)d_in[15];
    const float* mqbe  = (const float*)d_in[16];
    const float* mkW   = (const float*)d_in[17];
    const float* mkb   = (const float*)d_in[18];
    const float* mkg   = (const float*)d_in[19];
    const float* mkbe  = (const float*)d_in[20];
    float* out = (float*)d_out;

    if (!g_s1) {
        cudaStreamCreateWithFlags(&g_s1, cudaStreamNonBlocking);
        cudaEventCreateWithFlags(&g_evA, cudaEventDisableTiming);
        cudaEventCreateWithFlags(&g_evB, cudaEventDisableTiming);
    }

    float *q, *kk, *vv, *rfk, *beta;
    cudaGetSymbolAddress((void**)&q,    g_q);
    cudaGetSymbolAddress((void**)&kk,   g_k);
    cudaGetSymbolAddress((void**)&vv,   g_v);
    cudaGetSymbolAddress((void**)&rfk,  g_rfk);
    cudaGetSymbolAddress((void**)&beta, g_beta);

    __half *qH, *attH, *kdsH, *kdsL, *vdsH, *vdsL;
    __half *keyTH, *valTH, *kdH, *kdL, *vdH, *vdL;
    __half *wqTH, *wkTH, *wvTH, *woTH;
    cudaGetSymbolAddress((void**)&qH,    g_qH);
    cudaGetSymbolAddress((void**)&attH,  g_attH);
    cudaGetSymbolAddress((void**)&kdsH,  g_kdsH);
    cudaGetSymbolAddress((void**)&kdsL,  g_kdsL);
    cudaGetSymbolAddress((void**)&vdsH,  g_vdsH);
    cudaGetSymbolAddress((void**)&vdsL,  g_vdsL);
    cudaGetSymbolAddress((void**)&keyTH, g_keyTH);
    cudaGetSymbolAddress((void**)&valTH, g_valTH);
    cudaGetSymbolAddress((void**)&kdH,   g_kdH);
    cudaGetSymbolAddress((void**)&kdL,   g_kdL);
    cudaGetSymbolAddress((void**)&vdH,   g_vdH);
    cudaGetSymbolAddress((void**)&vdL,   g_vdL);
    cudaGetSymbolAddress((void**)&wqTH,  g_wqTH);
    cudaGetSymbolAddress((void**)&wkTH,  g_wkTH);
    cudaGetSymbolAddress((void**)&wvTH,  g_wvTH);
    cudaGetSymbolAddress((void**)&woTH,  g_woTH);

    cudaFuncSetAttribute(gemm_mma<1, 0>, cudaFuncAttributeMaxDynamicSharedMemorySize, GSMEM);
    cudaFuncSetAttribute(gemm_mma<4, 0>, cudaFuncAttributeMaxDynamicSharedMemorySize, GSMEM);
    cudaFuncSetAttribute(gemm_mma<4, 1>, cudaFuncAttributeMaxDynamicSharedMemorySize, GSMEM);

    // ================= fork: side stream handles the KV chain =================
    cudaEventRecord(g_evA, 0);
    cudaStreamWaitEvent(g_s1, g_evA, 0);

    // ---- side stream (g_s1): KV chain ----
    {
        long long t4 = (long long)Kx * Nx / 4;
        convert16<<<(unsigned)((t4 + 255) / 256), 256, 0, g_s1>>>(kds, kdsH, kdsL, t4);
        convert16<<<(unsigned)((t4 + 255) / 256), 256, 0, g_s1>>>(vds, vdsH, vdsL, t4);
    }
    transpose16<<<dim3(Cx / 64, Cx / 64, 1), 256, 0, g_s1>>>(Wk, wkTH, Cx, Cx, 0, 0);
    transpose16<<<dim3(Cx / 64, Cx / 64, 1), 256, 0, g_s1>>>(Wv, wvTH, Cx, Cx, 0, 0);
    transpose16<<<dim3(Cx / 64, Nx / 64, Bx), 256, 0, g_s1>>>(key, keyTH, Nx, Cx,
        (long long)Nx * Cx, (long long)Cx * Nx);
    transpose16<<<dim3(Cx / 64, Nx / 64, Bx), 256, 0, g_s1>>>(value, valTH, Nx, Cx,
        (long long)Nx * Cx, (long long)Cx * Nx);
    // downsample (TERMS=4: kds split, key/value hi) -> fp16 hi/lo plane out
    gemm_mma<4, 1><<<dim3(Cx / 128, 1, Bx), 256, GSMEM, g_s1>>>(
        kdsH, kdsL, keyTH, nullptr, nullptr, nullptr, kdH, kdL,
        Kx, Cx, Nx, 0, (long long)Cx * Nx, (long long)Kx * Cx);
    gemm_mma<4, 1><<<dim3(Cx / 128, 1, Bx), 256, GSMEM, g_s1>>>(
        vdsH, vdsL, valTH, nullptr, nullptr, nullptr, vdH, vdL,
        Kx, Cx, Nx, 0, (long long)Cx * Nx, (long long)Kx * Cx);
    // k/v projections (TERMS=4: key_d split, W hi) -> fp32
    gemm_mma<4, 0><<<dim3(Cx / 128, (Bx * Kx) / 128, 1), 256, GSMEM, g_s1>>>(
        kdH, kdL, wkTH, nullptr, bk, kk, nullptr, nullptr,
        Bx * Kx, Cx, Cx, 0, 0, 0);
    gemm_mma<4, 0><<<dim3(Cx / 128, (Bx * Kx) / 128, 1), 256, GSMEM, g_s1>>>(
        vdH, vdL, wvTH, nullptr, bv, vv, nullptr, nullptr,
        Bx * Kx, Cx, Cx, 0, 0, 0);
    cudaEventRecord(g_evB, g_s1);

    // ---- main stream: Q chain ----
    {
        long long t4 = (long long)Bx * Nx * Cx / 4;
        convert16<<<(unsigned)((t4 + 255) / 256), 256>>>(query, qH, nullptr, t4);
    }
    transpose16<<<dim3(Cx / 64, Cx / 64, 1), 256>>>(Wq, wqTH, Cx, Cx, 0, 0);
    transpose16<<<dim3(Cx / 64, Cx / 64, 1), 256>>>(Wo, woTH, Cx, Cx, 0, 0);

    // q = query @ Wq + bq : M=65536, N=768, K=768 -> fp32 (1-term pure fp16)
    gemm_mma<1, 0><<<dim3(Cx / 128, (Bx * Nx) / 128, 1), 256, GSMEM>>>(
        qH, nullptr, wqTH, nullptr, bq, q, nullptr, nullptr,
        Bx * Nx, Cx, Cx, 0, 0, 0);

    // ================= join =================
    cudaStreamWaitEvent(0, g_evB, 0);

    // chunk summaries + attention
    chunk_stats<<<Bx * Hx * 32, 64>>>(q, kk, vv,
                                      mqW, mqb, mqg, mqbe,
                                      mkW, mkb, mkg, mkbe,
                                      rfk, beta);
    attn_kernel<<<Bx * Hx * 32, 256>>>(q, kk, vv, rfk, beta, attH);

    // out = att @ Wo + bo : M=65536, N=768, K=768 -> fp32 (1-term pure fp16)
    gemm_mma<1, 0><<<dim3(Cx / 128, (Bx * Nx) / 128, 1), 256, GSMEM>>>(
        attH, nullptr, woTH, nullptr, bo, out, nullptr, nullptr,
        Bx * Nx, Cx, Cx, 0, 0, 0);
}

// round 13
// speedup vs baseline: 1.4398x; 1.0611x over previous
#include <cuda_runtime.h>
#include <cuda_fp16.h>
#include <math.h>
#include <stdint.h>

// Problem constants
#define Bx   64
#define Nx   1024
#define Cx   768
#define Hx   12
#define DHx  64
#define Kx   64
#define SCALEx 0.125f
#define LN_EPSx 1e-6f

// ------------------------- device scratch -------------------------
__device__ float g_q   [(long long)Bx * Nx * Cx];
__device__ float g_k   [(long long)Bx * Kx * Cx];
__device__ float g_v   [(long long)Bx * Kx * Cx];
__device__ float g_rfk [(long long)Bx * Hx * 32 * DHx];
__device__ float g_beta[(long long)Bx * Hx * 32 * DHx];

// fp16 planes (row-major)
__device__ __half g_qH   [(long long)Bx * Nx * Cx];
__device__ __half g_attH [(long long)Bx * Nx * Cx];
__device__ __half g_kdsH [Kx * Nx];
__device__ __half g_vdsH [Kx * Nx];
__device__ __half g_keyTH[(long long)Bx * Cx * Nx];
__device__ __half g_valTH[(long long)Bx * Cx * Nx];
__device__ __half g_kdH  [(long long)Bx * Kx * Cx];
__device__ __half g_vdH  [(long long)Bx * Kx * Cx];
__device__ __half g_wqTH [Cx * Cx];
__device__ __half g_wkTH [Cx * Cx];
__device__ __half g_wvTH [Cx * Cx];
__device__ __half g_woTH [Cx * Cx];

// ------------------------- helpers -------------------------
__device__ __forceinline__ uint32_t smem_u32(const void* p) {
    uint32_t a;
    asm("{ .reg .u64 t; cvta.to.shared.u64 t, %1; cvt.u32.u64 %0, t; }" : "=r"(a) : "l"(p));
    return a;
}
__device__ __forceinline__ void cp16(uint32_t dst, const void* src, int srcsz) {
    asm volatile("cp.async.cg.shared.global [%0], [%1], 16, %2;"
                 :: "r"(dst), "l"(src), "r"(srcsz) : "memory");
}
#define CP_COMMIT() asm volatile("cp.async.commit_group;" ::: "memory")
#define CP_WAIT1()  asm volatile("cp.async.wait_group 1;" ::: "memory")
#define CP_WAIT0()  asm volatile("cp.async.wait_group 0;" ::: "memory")

__device__ __forceinline__ void ldm_x4(uint32_t* r, uint32_t a) {
    asm volatile("ldmatrix.sync.aligned.m8n8.x4.shared.b16 {%0,%1,%2,%3}, [%4];"
                 : "=r"(r[0]), "=r"(r[1]), "=r"(r[2]), "=r"(r[3]) : "r"(a));
}
__device__ __forceinline__ void mma_f16(float* d, const uint32_t* a, const uint32_t* b) {
    asm volatile("mma.sync.aligned.m16n8k16.row.col.f32.f16.f16.f32 "
                 "{%0,%1,%2,%3},{%4,%5,%6,%7},{%8,%9},{%0,%1,%2,%3};"
                 : "+f"(d[0]), "+f"(d[1]), "+f"(d[2]), "+f"(d[3])
                 : "r"(a[0]), "r"(a[1]), "r"(a[2]), "r"(a[3]), "r"(b[0]), "r"(b[1]));
}

// ------------------------- convert (row-major, hi only) -------------------------
__global__ __launch_bounds__(256)
void convert16(const float* __restrict__ in,
               __half* __restrict__ oh,
               long long total4)
{
    const long long g = (long long)blockIdx.x * 256 + threadIdx.x;
    if (g >= total4) return;
    float4 f = ((const float4*)in)[g];
    __half h[4];
    h[0] = __float2half(f.x); h[1] = __float2half(f.y);
    h[2] = __float2half(f.z); h[3] = __float2half(f.w);
    *(uint2*)(oh + g * 4) = *(uint2*)h;
}

// ------------------------- transpose (hi plane only) ------------
__global__ __launch_bounds__(256)
void transpose16(const float* __restrict__ in,
                 __half* __restrict__ oh,
                 int R, int Cc, long long sIn, long long sOut)
{
    __shared__ float t[64][65];
    in += (long long)blockIdx.z * sIn;
    oh += (long long)blockIdx.z * sOut;
    const int r0 = blockIdx.y * 64;
    const int c0 = blockIdx.x * 64;
    const int tid = threadIdx.x;
    #pragma unroll
    for (int it = 0; it < 4; it++) {
        const int idx = it * 256 + tid;
        const int row = idx >> 4;
        const int c4  = (idx & 15) * 4;
        float4 f = *(const float4*)(in + (long long)(r0 + row) * Cc + c0 + c4);
        t[row][c4 + 0] = f.x; t[row][c4 + 1] = f.y;
        t[row][c4 + 2] = f.z; t[row][c4 + 3] = f.w;
    }
    __syncthreads();
    #pragma unroll
    for (int it = 0; it < 2; it++) {
        const int idx = it * 256 + tid;
        const int oc = idx >> 3;
        const int k8 = (idx & 7) * 8;
        __half h[8];
        #pragma unroll
        for (int j = 0; j < 8; j++)
            h[j] = __float2half(t[k8 + j][oc]);
        const long long base = (long long)(c0 + oc) * R + r0 + k8;
        *(uint4*)(oh + base) = *(uint4*)h;
    }
}

// ------------------------- mma.sync GEMM (fp16, ldmatrix) -------------------
// TERMS=1: ah*bh (pure fp16).
// MODE 0: fp32 out (+bias); MODE 2: fp16 hi-only out.
#define TSB 80
#define PLB 10240
#define BUFB 40960
#define GSMEM (2 * BUFB)

template<int TERMS, int MODE>
__global__ __launch_bounds__(256)
void gemm_mma(const __half* __restrict__ Ah,
              const __half* __restrict__ Bh,
              const float* __restrict__ bias,
              float* __restrict__ Cf,
              __half* __restrict__ Ch,
              int M, int Nn, int Kk,
              long long sA, long long sB, long long sC)
{
    extern __shared__ char sm[];
    const long long z = blockIdx.z;
    Ah += z * sA;
    Bh += z * sB;

    const int bRow = blockIdx.y * 128;
    const int bCol = blockIdx.x * 128;
    const int tid  = threadIdx.x;
    const int lane = tid & 31;
    const int wid  = tid >> 5;
    const int warpRow = (wid & 3) * 32;
    const int warpCol = (wid >> 2) * 64;
    const uint32_t sb = smem_u32(sm);

    float acc[2][8][4];
    #pragma unroll
    for (int i = 0; i < 2; i++)
        #pragma unroll
        for (int j = 0; j < 8; j++)
            #pragma unroll
            for (int r = 0; r < 4; r++) acc[i][j][r] = 0.f;

    const int nCh = Kk / 32;

    auto loadChunk = [&](int c, int buf) {
        const int k0 = c * 32;
        const uint32_t d = sb + buf * BUFB;
        #pragma unroll
        for (int s2 = 0; s2 < 2; s2++) {
            const int row = s2 * 64 + (tid >> 2);
            const int g   = tid & 3;
            const uint32_t doff = row * TSB + g * 16;
            const int ar = bRow + row;
            const int sz = (ar < M) ? 16 : 0;
            const long long aoff = (long long)((ar < M) ? ar : 0) * Kk + k0 + g * 8;
            cp16(d + doff, Ah + aoff, sz);
            const long long boff = (long long)(bCol + row) * Kk + k0 + g * 8;
            cp16(d + 2 * PLB + doff, Bh + boff, 16);
        }
        CP_COMMIT();
    };

    const int aRowSel = (lane & 15);
    const int aKHalf  = (lane >> 4) & 1;
    const int bRowSel = (lane & 7) + ((lane >> 4) & 1) * 8;
    const int bKHalf  = (lane >> 3) & 1;

    loadChunk(0, 0);
    for (int c = 0; c < nCh; c++) {
        const int buf = c & 1;
        if (c + 1 < nCh) { loadChunk(c + 1, buf ^ 1); CP_WAIT1(); }
        else             { CP_WAIT0(); }
        __syncthreads();

        const uint32_t aT = sb + buf * BUFB;
        const uint32_t bT = aT + 2 * PLB;

        #pragma unroll
        for (int s = 0; s < 2; s++) {
            const int kb = s * 32;
            uint32_t ah[2][4];
            #pragma unroll
            for (int i = 0; i < 2; i++) {
                const uint32_t ad = aT + (warpRow + i * 16 + aRowSel) * TSB
                                       + kb + aKHalf * 16;
                ldm_x4(ah[i], ad);
            }
            #pragma unroll
            for (int jp = 0; jp < 4; jp++) {
                const uint32_t bd = bT + (warpCol + jp * 16 + bRowSel) * TSB
                                       + kb + bKHalf * 16;
                uint32_t bh[4];
                ldm_x4(bh, bd);
                #pragma unroll
                for (int jj = 0; jj < 2; jj++) {
                    #pragma unroll
                    for (int i = 0; i < 2; i++) {
                        mma_f16(acc[i][2 * jp + jj], ah[i], &bh[2 * jj]);
                    }
                }
            }
        }
        __syncthreads();
    }

    // ------------- epilogue -------------
    const int rB = bRow + warpRow + (lane >> 2);
    if (MODE == 0) {
        float* C = Cf + z * sC;
        #pragma unroll
        for (int i = 0; i < 2; i++) {
            #pragma unroll
            for (int j = 0; j < 8; j++) {
                const int col = bCol + warpCol + j * 8 + (lane & 3) * 2;
                float bx = 0.f, by = 0.f;
                if (bias) { bx = bias[col]; by = bias[col + 1]; }
                const int r = rB + i * 16;
                if (r < M) {
                    float2 o = make_float2(acc[i][j][0] + bx, acc[i][j][1] + by);
                    *(float2*)(C + (long long)r * Nn + col) = o;
                }
                if (r + 8 < M) {
                    float2 o = make_float2(acc[i][j][2] + bx, acc[i][j][3] + by);
                    *(float2*)(C + (long long)(r + 8) * Nn + col) = o;
                }
            }
        }
    } else {
        __half* CH = Ch + z * sC;
        #pragma unroll
        for (int i = 0; i < 2; i++) {
            #pragma unroll
            for (int j = 0; j < 8; j++) {
                const int col = bCol + warpCol + j * 8 + (lane & 3) * 2;
                #pragma unroll
                for (int half = 0; half < 2; half++) {
                    const int r = rB + i * 16 + half * 8;
                    if (r >= M) continue;
                    __half hp[2];
                    hp[0] = __float2half(acc[i][j][2 * half + 0]);
                    hp[1] = __float2half(acc[i][j][2 * half + 1]);
                    *(uint32_t*)(CH + (long long)r * Nn + col) = *(uint32_t*)hp;
                }
            }
        }
    }
}

// ------------------------- chunk stats -------------------------
__device__ __forceinline__ float blk_reduce64(float x, float* red)
{
    const int d = threadIdx.x;
    #pragma unroll
    for (int o = 16; o > 0; o >>= 1)
        x += __shfl_down_sync(0xffffffffu, x, o);
    if ((d & 31) == 0) red[d >> 5] = x;
    __syncthreads();
    const float r = red[0] + red[1];
    __syncthreads();
    return r;
}

__global__ __launch_bounds__(64)
void chunk_stats(const float* __restrict__ q, const float* __restrict__ k,
                 const float* __restrict__ v,
                 const float* __restrict__ mqW, const float* __restrict__ mqb,
                 const float* __restrict__ mqg, const float* __restrict__ mqbe,
                 const float* __restrict__ mkW, const float* __restrict__ mkb,
                 const float* __restrict__ mkg, const float* __restrict__ mkbe,
                 float* __restrict__ rfk, float* __restrict__ beta)
{
    const int blk = blockIdx.x;
    const int c  = blk & 31;
    const int bh = blk >> 5;
    const int h  = bh % Hx;
    const int b  = bh / Hx;
    const int d  = threadIdx.x;

    __shared__ float qm[64], km[64], k0s[64], k1s[64], v0s[64], v1s[64];
    __shared__ float red[2];
    __shared__ float probs[2];

    {
        const float* qb = q + ((long long)(b * Nx + c * 32)) * Cx + h * DHx + d;
        float s = 0.f;
        #pragma unroll 8
        for (int i = 0; i < 32; i++) s += qb[(long long)i * Cx];
        qm[d] = s * (1.f / 32.f);
    }
    {
        const float* kb = k + ((long long)(b * Kx + c * 2)) * Cx + h * DHx + d;
        const float k0v = kb[0], k1v = kb[Cx];
        k0s[d] = k0v; k1s[d] = k1v;
        km[d]  = 0.5f * (k0v + k1v);
        const float* vb = v + ((long long)(b * Kx + c * 2)) * Cx + h * DHx + d;
        v0s[d] = vb[0]; v1s[d] = vb[Cx];
    }
    __syncthreads();

    float yq = mqb[d], yk = mkb[d];
    #pragma unroll 8
    for (int e = 0; e < 64; e++) {
        yq = fmaf(qm[e], mqW[e * 64 + d], yq);
        yk = fmaf(km[e], mkW[e * 64 + d], yk);
    }

    float m  = blk_reduce64(yq, red) * (1.f / 64.f);
    float dv = yq - m;
    float var = blk_reduce64(dv * dv, red) * (1.f / 64.f);
    const float qbar = dv * rsqrtf(var + LN_EPSx) * mqg[d] + mqbe[d];

    m  = blk_reduce64(yk, red) * (1.f / 64.f);
    dv = yk - m;
    var = blk_reduce64(dv * dv, red) * (1.f / 64.f);
    const float kbar = dv * rsqrtf(var + LN_EPSx) * mkg[d] + mkbe[d];

    rfk[((long long)bh * 32 + c) * 64 + d] = kbar;

    const float mu = 0.5f * (qbar + kbar);

    const float s0 = blk_reduce64(mu * k0s[d], red);
    const float n0 = blk_reduce64(k0s[d] * k0s[d], red);
    const float s1 = blk_reduce64(mu * k1s[d], red);
    const float n1 = blk_reduce64(k1s[d] * k1s[d], red);

    if (d == 0) {
        const float dn = 0.125f;
        const float l0 = dn * s0 - 0.5f * dn * n0;
        const float l1 = dn * s1 - 0.5f * dn * n1;
        const float mx = fmaxf(l0, l1);
        const float e0 = expf(l0 - mx);
        const float e1 = expf(l1 - mx);
        const float inv = 1.f / (e0 + e1);
        probs[0] = e0 * inv;
        probs[1] = e1 * inv;
    }
    __syncthreads();

    beta[((long long)bh * 32 + c) * 64 + d] = probs[0] * v0s[d] + probs[1] * v1s[d];
}

// ------------------------- attention (fp16 hi output) -------------------------
__global__ __launch_bounds__(256)
void attn_kernel(const float* __restrict__ q, const float* __restrict__ k,
                 const float* __restrict__ v,
                 const float* __restrict__ rfk, const float* __restrict__ betag,
                 __half* __restrict__ outH)
{
    const int blk = blockIdx.x;
    const int w  = blk & 31;
    const int bh = blk >> 5;
    const int h  = bh % Hx;
    const int b  = bh / Hx;

    __shared__ float qs [32][65];
    __shared__ float kbs[32][64];
    __shared__ float bes[32][64];
    __shared__ float wks[2][64];
    __shared__ float wvs[2][64];
    __shared__ float lg [32][35];

    const int t = threadIdx.x;

    for (int idx = t; idx < 2048; idx += 256) {
        const int i = idx >> 6, d = idx & 63;
        qs [i][d] = q    [((long long)(b * Nx + w * 32 + i)) * Cx + h * DHx + d];
        kbs[i][d] = rfk  [((long long)bh * 32 + i) * 64 + d];
        bes[i][d] = betag[((long long)bh * 32 + i) * 64 + d];
    }
    if (t < 128) {
        const int j = t >> 6, d = t & 63;
        wks[j][d] = k[((long long)(b * Kx + w * 2 + j)) * Cx + h * DHx + d];
        wvs[j][d] = v[((long long)(b * Kx + w * 2 + j)) * Cx + h * DHx + d];
    }
    __syncthreads();

    {
        const int i   = t & 31;
        const int sl0 = t >> 5;
        for (int slot = sl0; slot < 34; slot += 8) {
            const float* kv = (slot < 2) ? &wks[slot][0] : &kbs[slot - 2][0];
            float s = 0.f;
            #pragma unroll
            for (int e = 0; e < 64; e++) s = fmaf(qs[i][e], kv[e], s);
            lg[i][slot] = s * SCALEx;
        }
    }
    __syncthreads();

    if (t < 32) {
        float mx = -1e30f;
        #pragma unroll
        for (int s = 0; s < 34; s++) mx = fmaxf(mx, lg[t][s]);
        float sum = 0.f;
        #pragma unroll
        for (int s = 0; s < 34; s++) { const float e = expf(lg[t][s] - mx); lg[t][s] = e; sum += e; }
        const float inv = 1.f / sum;
        #pragma unroll
        for (int s = 0; s < 34; s++) lg[t][s] *= inv;
    }
    __syncthreads();

    const int d = t & 63;
    #pragma unroll
    for (int p = 0; p < 8; p++) {
        const int ii = p * 4 + (t >> 6);
        float acc = lg[ii][0] * wvs[0][d] + lg[ii][1] * wvs[1][d];
        #pragma unroll
        for (int c2 = 0; c2 < 32; c2++)
            acc = fmaf(lg[ii][2 + c2], bes[c2][d], acc);
        const long long ro = ((long long)(b * Nx + w * 32 + ii)) * Cx + h * DHx + d;
        outH[ro] = __float2half(acc);
    }
}

// ------------------------- launch -------------------------
static cudaStream_t g_s1 = nullptr;
static cudaEvent_t  g_evA = nullptr, g_evB = nullptr;

extern "C" void kernel_launch(void* const* d_in, const int* in_sizes, int n_in,
                              void* d_out, int out_size)
{
    const float* query = (const float*)d_in[0];
    const float* key   = (const float*)d_in[1];
    const float* value = (const float*)d_in[2];
    const float* Wq    = (const float*)d_in[3];
    const float* bq    = (const float*)d_in[4];
    const float* Wk    = (const float*)d_in[5];
    const float* bk    = (const float*)d_in[6];
    const float* Wv    = (const float*)d_in[7];
    const float* bv    = (const float*)d_in[8];
    const float* Wo    = (const float*)d_in[9];
    const float* bo    = (const float*)d_in[10];
    const float* kds   = (const float*)d_in[11];
    const float* vds   = (const float*)d_in[12];
    const float* mqW   = (const float*)d_in[13];
    const float* mqb   = (const float*)d_in[14];
    const float* mqg   = (const float*)d_in[15];
    const float* mqbe  = (const float*)d_in[16];
    const float* mkW   = (const float*)d_in[17];
    const float* mkb   = (const float*)d_in[18];
    const float* mkg   = (const float*)d_in[19];
    const float* mkbe  = (const float*)d_in[20];
    float* out = (float*)d_out;

    if (!g_s1) {
        cudaStreamCreateWithFlags(&g_s1, cudaStreamNonBlocking);
        cudaEventCreateWithFlags(&g_evA, cudaEventDisableTiming);
        cudaEventCreateWithFlags(&g_evB, cudaEventDisableTiming);
    }

    float *q, *kk, *vv, *rfk, *beta;
    cudaGetSymbolAddress((void**)&q,    g_q);
    cudaGetSymbolAddress((void**)&kk,   g_k);
    cudaGetSymbolAddress((void**)&vv,   g_v);
    cudaGetSymbolAddress((void**)&rfk,  g_rfk);
    cudaGetSymbolAddress((void**)&beta, g_beta);

    __half *qH, *attH, *kdsH, *vdsH;
    __half *keyTH, *valTH, *kdH, *vdH;
    __half *wqTH, *wkTH, *wvTH, *woTH;
    cudaGetSymbolAddress((void**)&qH,    g_qH);
    cudaGetSymbolAddress((void**)&attH,  g_attH);
    cudaGetSymbolAddress((void**)&kdsH,  g_kdsH);
    cudaGetSymbolAddress((void**)&vdsH,  g_vdsH);
    cudaGetSymbolAddress((void**)&keyTH, g_keyTH);
    cudaGetSymbolAddress((void**)&valTH, g_valTH);
    cudaGetSymbolAddress((void**)&kdH,   g_kdH);
    cudaGetSymbolAddress((void**)&vdH,   g_vdH);
    cudaGetSymbolAddress((void**)&wqTH,  g_wqTH);
    cudaGetSymbolAddress((void**)&wkTH,  g_wkTH);
    cudaGetSymbolAddress((void**)&wvTH,  g_wvTH);
    cudaGetSymbolAddress((void**)&woTH,  g_woTH);

    cudaFuncSetAttribute(gemm_mma<1, 0>, cudaFuncAttributeMaxDynamicSharedMemorySize, GSMEM);
    cudaFuncSetAttribute(gemm_mma<1, 2>, cudaFuncAttributeMaxDynamicSharedMemorySize, GSMEM);

    // fork event for graph capture (side-stream work reachable from origin)
    cudaEventRecord(g_evA, 0);
    cudaStreamWaitEvent(g_s1, g_evA, 0);

    // ---- launches 1-5: main-chain prep + two tiny side converts ----
    {
        long long t4 = (long long)Bx * Nx * Cx / 4;
        convert16<<<(unsigned)((t4 + 255) / 256), 256>>>(query, qH, t4);               // 1
    }
    transpose16<<<dim3(Cx / 64, Cx / 64, 1), 256>>>(Wq, wqTH, Cx, Cx, 0, 0);           // 2
    transpose16<<<dim3(Cx / 64, Cx / 64, 1), 256>>>(Wo, woTH, Cx, Cx, 0, 0);           // 3
    {
        long long t4 = (long long)Kx * Nx / 4;
        convert16<<<(unsigned)((t4 + 255) / 256), 256, 0, g_s1>>>(kds, kdsH, t4);      // 4
        convert16<<<(unsigned)((t4 + 255) / 256), 256, 0, g_s1>>>(vds, vdsH, t4);      // 5
    }

    // ---- launch 6 (ncu target): q = query @ Wq + bq (pure fp16) ----
    gemm_mma<1, 0><<<dim3(Cx / 128, (Bx * Nx) / 128, 1), 256, GSMEM>>>(
        qH, wqTH, bq, q, nullptr,
        Bx * Nx, Cx, Cx, 0, 0, 0);

    // ---- side stream: rest of KV chain ----
    transpose16<<<dim3(Cx / 64, Cx / 64, 1), 256, 0, g_s1>>>(Wk, wkTH, Cx, Cx, 0, 0);
    transpose16<<<dim3(Cx / 64, Cx / 64, 1), 256, 0, g_s1>>>(Wv, wvTH, Cx, Cx, 0, 0);
    transpose16<<<dim3(Cx / 64, Nx / 64, Bx), 256, 0, g_s1>>>(key, keyTH, Nx, Cx,
        (long long)Nx * Cx, (long long)Cx * Nx);
    transpose16<<<dim3(Cx / 64, Nx / 64, Bx), 256, 0, g_s1>>>(value, valTH, Nx, Cx,
        (long long)Nx * Cx, (long long)Cx * Nx);
    // downsample (pure fp16) -> fp16 hi out
    gemm_mma<1, 2><<<dim3(Cx / 128, 1, Bx), 256, GSMEM, g_s1>>>(
        kdsH, keyTH, nullptr, nullptr, kdH,
        Kx, Cx, Nx, 0, (long long)Cx * Nx, (long long)Kx * Cx);
    gemm_mma<1, 2><<<dim3(Cx / 128, 1, Bx), 256, GSMEM, g_s1>>>(
        vdsH, valTH, nullptr, nullptr, vdH,
        Kx, Cx, Nx, 0, (long long)Cx * Nx, (long long)Kx * Cx);
    // k/v projections (pure fp16) -> fp32
    gemm_mma<1, 0><<<dim3(Cx / 128, (Bx * Kx) / 128, 1), 256, GSMEM, g_s1>>>(
        kdH, wkTH, bk, kk, nullptr,
        Bx * Kx, Cx, Cx, 0, 0, 0);
    gemm_mma<1, 0><<<dim3(Cx / 128, (Bx * Kx) / 128, 1), 256, GSMEM, g_s1>>>(
        vdH, wvTH, bv, vv, nullptr,
        Bx * Kx, Cx, Cx, 0, 0, 0);
    cudaEventRecord(g_evB, g_s1);

    // ================= join =================
    cudaStreamWaitEvent(0, g_evB, 0);

    // chunk summaries + attention
    chunk_stats<<<Bx * Hx * 32, 64>>>(q, kk, vv,
                                      mqW, mqb, mqg, mqbe,
                                      mkW, mkb, mkg, mkbe,
                                      rfk, beta);
    attn_kernel<<<Bx * Hx * 32, 256>>>(q, kk, vv, rfk, beta, attH);

    // out = att @ Wo + bo (pure fp16)
    gemm_mma<1, 0><<<dim3(Cx / 128, (Bx * Nx) / 128, 1), 256, GSMEM>>>(
        attH, woTH, bo, out, nullptr,
        Bx * Nx, Cx, Cx, 0, 0, 0);
}

// round 14
// speedup vs baseline: 1.4661x; 1.0182x over previous
#include <cuda_runtime.h>
#include <cuda_fp16.h>
#include <math.h>
#include <stdint.h>

// Problem constants
#define Bx   64
#define Nx   1024
#define Cx   768
#define Hx   12
#define DHx  64
#define Kx   64
#define SCALEx 0.125f
#define LN_EPSx 1e-6f

// ------------------------- device scratch -------------------------
__device__ float g_k    [(long long)Bx * Kx * Cx];
__device__ float g_v    [(long long)Bx * Kx * Cx];
__device__ float g_qmean[(long long)Bx * Hx * 32 * DHx];
__device__ float g_rfk  [(long long)Bx * Hx * 32 * DHx];
__device__ float g_beta [(long long)Bx * Hx * 32 * DHx];

// fp16 planes (row-major)
__device__ __half g_qinH [(long long)Bx * Nx * Cx];   // query input, fp16
__device__ __half g_qH   [(long long)Bx * Nx * Cx];   // q projection out, fp16 (with bias)
__device__ __half g_attH [(long long)Bx * Nx * Cx];
__device__ __half g_kdsH [Kx * Nx];
__device__ __half g_vdsH [Kx * Nx];
__device__ __half g_keyTH[(long long)Bx * Cx * Nx];
__device__ __half g_valTH[(long long)Bx * Cx * Nx];
__device__ __half g_kdH  [(long long)Bx * Kx * Cx];
__device__ __half g_vdH  [(long long)Bx * Kx * Cx];
__device__ __half g_wqTH [Cx * Cx];
__device__ __half g_wkTH [Cx * Cx];
__device__ __half g_wvTH [Cx * Cx];
__device__ __half g_woTH [Cx * Cx];

// ------------------------- helpers -------------------------
__device__ __forceinline__ uint32_t smem_u32(const void* p) {
    uint32_t a;
    asm("{ .reg .u64 t; cvta.to.shared.u64 t, %1; cvt.u32.u64 %0, t; }" : "=r"(a) : "l"(p));
    return a;
}
__device__ __forceinline__ void cp16(uint32_t dst, const void* src, int srcsz) {
    asm volatile("cp.async.cg.shared.global [%0], [%1], 16, %2;"
                 :: "r"(dst), "l"(src), "r"(srcsz) : "memory");
}
#define CP_COMMIT() asm volatile("cp.async.commit_group;" ::: "memory")
#define CP_WAIT1()  asm volatile("cp.async.wait_group 1;" ::: "memory")
#define CP_WAIT0()  asm volatile("cp.async.wait_group 0;" ::: "memory")

__device__ __forceinline__ void ldm_x4(uint32_t* r, uint32_t a) {
    asm volatile("ldmatrix.sync.aligned.m8n8.x4.shared.b16 {%0,%1,%2,%3}, [%4];"
                 : "=r"(r[0]), "=r"(r[1]), "=r"(r[2]), "=r"(r[3]) : "r"(a));
}
__device__ __forceinline__ void mma_f16(float* d, const uint32_t* a, const uint32_t* b) {
    asm volatile("mma.sync.aligned.m16n8k16.row.col.f32.f16.f16.f32 "
                 "{%0,%1,%2,%3},{%4,%5,%6,%7},{%8,%9},{%0,%1,%2,%3};"
                 : "+f"(d[0]), "+f"(d[1]), "+f"(d[2]), "+f"(d[3])
                 : "r"(a[0]), "r"(a[1]), "r"(a[2]), "r"(a[3]), "r"(b[0]), "r"(b[1]));
}

// ------------------------- convert (row-major, hi only) -------------------------
__global__ __launch_bounds__(256)
void convert16(const float* __restrict__ in,
               __half* __restrict__ oh,
               long long total4)
{
    const long long g = (long long)blockIdx.x * 256 + threadIdx.x;
    if (g >= total4) return;
    float4 f = ((const float4*)in)[g];
    __half h[4];
    h[0] = __float2half(f.x); h[1] = __float2half(f.y);
    h[2] = __float2half(f.z); h[3] = __float2half(f.w);
    *(uint2*)(oh + g * 4) = *(uint2*)h;
}

// ------------------------- transpose (hi plane only) ------------
__global__ __launch_bounds__(256)
void transpose16(const float* __restrict__ in,
                 __half* __restrict__ oh,
                 int R, int Cc, long long sIn, long long sOut)
{
    __shared__ float t[64][65];
    in += (long long)blockIdx.z * sIn;
    oh += (long long)blockIdx.z * sOut;
    const int r0 = blockIdx.y * 64;
    const int c0 = blockIdx.x * 64;
    const int tid = threadIdx.x;
    #pragma unroll
    for (int it = 0; it < 4; it++) {
        const int idx = it * 256 + tid;
        const int row = idx >> 4;
        const int c4  = (idx & 15) * 4;
        float4 f = *(const float4*)(in + (long long)(r0 + row) * Cc + c0 + c4);
        t[row][c4 + 0] = f.x; t[row][c4 + 1] = f.y;
        t[row][c4 + 2] = f.z; t[row][c4 + 3] = f.w;
    }
    __syncthreads();
    #pragma unroll
    for (int it = 0; it < 2; it++) {
        const int idx = it * 256 + tid;
        const int oc = idx >> 3;
        const int k8 = (idx & 7) * 8;
        __half h[8];
        #pragma unroll
        for (int j = 0; j < 8; j++)
            h[j] = __float2half(t[k8 + j][oc]);
        const long long base = (long long)(c0 + oc) * R + r0 + k8;
        *(uint4*)(oh + base) = *(uint4*)h;
    }
}

// ------------------------- mma.sync GEMM (fp16, ldmatrix) -------------------
// MODE 0: fp32 out (+bias)
// MODE 2: fp16 out (no bias)
// MODE 3: fp16 out (+bias) AND per-32-row column means (+bias) into Cf
//         (qmean layout: ((b*H + h)*32 + c)*64 + d, requires M%128==0, Nn=768)
#define TSB 80
#define PLB 10240
#define BUFB 40960
#define GSMEM (2 * BUFB)

template<int MODE>
__global__ __launch_bounds__(256)
void gemm_mma(const __half* __restrict__ Ah,
              const __half* __restrict__ Bh,
              const float* __restrict__ bias,
              float* __restrict__ Cf,
              __half* __restrict__ Ch,
              int M, int Nn, int Kk,
              long long sA, long long sB, long long sC)
{
    extern __shared__ char sm[];
    const long long z = blockIdx.z;
    Ah += z * sA;
    Bh += z * sB;

    const int bRow = blockIdx.y * 128;
    const int bCol = blockIdx.x * 128;
    const int tid  = threadIdx.x;
    const int lane = tid & 31;
    const int wid  = tid >> 5;
    const int warpRow = (wid & 3) * 32;
    const int warpCol = (wid >> 2) * 64;
    const uint32_t sb = smem_u32(sm);

    float acc[2][8][4];
    #pragma unroll
    for (int i = 0; i < 2; i++)
        #pragma unroll
        for (int j = 0; j < 8; j++)
            #pragma unroll
            for (int r = 0; r < 4; r++) acc[i][j][r] = 0.f;

    const int nCh = Kk / 32;

    auto loadChunk = [&](int c, int buf) {
        const int k0 = c * 32;
        const uint32_t d = sb + buf * BUFB;
        #pragma unroll
        for (int s2 = 0; s2 < 2; s2++) {
            const int row = s2 * 64 + (tid >> 2);
            const int g   = tid & 3;
            const uint32_t doff = row * TSB + g * 16;
            const int ar = bRow + row;
            const int sz = (ar < M) ? 16 : 0;
            const long long aoff = (long long)((ar < M) ? ar : 0) * Kk + k0 + g * 8;
            cp16(d + doff, Ah + aoff, sz);
            const long long boff = (long long)(bCol + row) * Kk + k0 + g * 8;
            cp16(d + 2 * PLB + doff, Bh + boff, 16);
        }
        CP_COMMIT();
    };

    const int aRowSel = (lane & 15);
    const int aKHalf  = (lane >> 4) & 1;
    const int bRowSel = (lane & 7) + ((lane >> 4) & 1) * 8;
    const int bKHalf  = (lane >> 3) & 1;

    loadChunk(0, 0);
    for (int c = 0; c < nCh; c++) {
        const int buf = c & 1;
        if (c + 1 < nCh) { loadChunk(c + 1, buf ^ 1); CP_WAIT1(); }
        else             { CP_WAIT0(); }
        __syncthreads();

        const uint32_t aT = sb + buf * BUFB;
        const uint32_t bT = aT + 2 * PLB;

        #pragma unroll
        for (int s = 0; s < 2; s++) {
            const int kb = s * 32;
            uint32_t ah[2][4];
            #pragma unroll
            for (int i = 0; i < 2; i++) {
                const uint32_t ad = aT + (warpRow + i * 16 + aRowSel) * TSB
                                       + kb + aKHalf * 16;
                ldm_x4(ah[i], ad);
            }
            #pragma unroll
            for (int jp = 0; jp < 4; jp++) {
                const uint32_t bd = bT + (warpCol + jp * 16 + bRowSel) * TSB
                                       + kb + bKHalf * 16;
                uint32_t bh[4];
                ldm_x4(bh, bd);
                #pragma unroll
                for (int jj = 0; jj < 2; jj++) {
                    #pragma unroll
                    for (int i = 0; i < 2; i++) {
                        mma_f16(acc[i][2 * jp + jj], ah[i], &bh[2 * jj]);
                    }
                }
            }
        }
        __syncthreads();
    }

    // ------------- epilogue -------------
    const int rB = bRow + warpRow + (lane >> 2);
    if (MODE == 0) {
        float* C = Cf + z * sC;
        #pragma unroll
        for (int i = 0; i < 2; i++) {
            #pragma unroll
            for (int j = 0; j < 8; j++) {
                const int col = bCol + warpCol + j * 8 + (lane & 3) * 2;
                float bx = 0.f, by = 0.f;
                if (bias) { bx = bias[col]; by = bias[col + 1]; }
                const int r = rB + i * 16;
                if (r < M) {
                    float2 o = make_float2(acc[i][j][0] + bx, acc[i][j][1] + by);
                    *(float2*)(C + (long long)r * Nn + col) = o;
                }
                if (r + 8 < M) {
                    float2 o = make_float2(acc[i][j][2] + bx, acc[i][j][3] + by);
                    *(float2*)(C + (long long)(r + 8) * Nn + col) = o;
                }
            }
        }
    } else if (MODE == 2) {
        __half* CH = Ch + z * sC;
        #pragma unroll
        for (int i = 0; i < 2; i++) {
            #pragma unroll
            for (int j = 0; j < 8; j++) {
                const int col = bCol + warpCol + j * 8 + (lane & 3) * 2;
                #pragma unroll
                for (int half = 0; half < 2; half++) {
                    const int r = rB + i * 16 + half * 8;
                    if (r >= M) continue;
                    __half hp[2];
                    hp[0] = __float2half(acc[i][j][2 * half + 0]);
                    hp[1] = __float2half(acc[i][j][2 * half + 1]);
                    *(uint32_t*)(CH + (long long)r * Nn + col) = *(uint32_t*)hp;
                }
            }
        }
    } else {  // MODE == 3: fp16 (+bias) out + column means into Cf (qmean)
        __half* CH = Ch;
        #pragma unroll
        for (int i = 0; i < 2; i++) {
            #pragma unroll
            for (int j = 0; j < 8; j++) {
                const int col = bCol + warpCol + j * 8 + (lane & 3) * 2;
                const float bx = bias[col], by = bias[col + 1];
                #pragma unroll
                for (int half = 0; half < 2; half++) {
                    const int r = rB + i * 16 + half * 8;
                    __half hp[2];
                    hp[0] = __float2half(acc[i][j][2 * half + 0] + bx);
                    hp[1] = __float2half(acc[i][j][2 * half + 1] + by);
                    *(uint32_t*)(CH + (long long)r * Nn + col) = *(uint32_t*)hp;
                }
            }
        }
        // per-(chunk=warpRow block, head=warpCol block) column means
        const int rowBase = bRow + warpRow;           // multiple of 32
        const int b = rowBase >> 10;                   // /1024
        const int c = (rowBase >> 5) & 31;             // chunk within batch
        #pragma unroll
        for (int j = 0; j < 8; j++) {
            float s0 = acc[0][j][0] + acc[0][j][2] + acc[1][j][0] + acc[1][j][2];
            float s1 = acc[0][j][1] + acc[0][j][3] + acc[1][j][1] + acc[1][j][3];
            #pragma unroll
            for (int o = 16; o >= 4; o >>= 1) {
                s0 += __shfl_down_sync(0xffffffffu, s0, o);
                s1 += __shfl_down_sync(0xffffffffu, s1, o);
            }
            if ((lane >> 2) == 0) {
                const int col = bCol + warpCol + j * 8 + lane * 2;
                const int h = col >> 6, d = col & 63;
                float* qm = Cf + (((long long)(b * Hx + h)) * 32 + c) * 64 + d;
                qm[0] = s0 * (1.f / 32.f) + bias[col];
                qm[1] = s1 * (1.f / 32.f) + bias[col + 1];
            }
        }
    }
}

// ------------------------- chunk stats -------------------------
__device__ __forceinline__ float blk_reduce64(float x, float* red)
{
    const int d = threadIdx.x;
    #pragma unroll
    for (int o = 16; o > 0; o >>= 1)
        x += __shfl_down_sync(0xffffffffu, x, o);
    if ((d & 31) == 0) red[d >> 5] = x;
    __syncthreads();
    const float r = red[0] + red[1];
    __syncthreads();
    return r;
}

__global__ __launch_bounds__(64)
void chunk_stats(const float* __restrict__ qmean, const float* __restrict__ k,
                 const float* __restrict__ v,
                 const float* __restrict__ mqW, const float* __restrict__ mqb,
                 const float* __restrict__ mqg, const float* __restrict__ mqbe,
                 const float* __restrict__ mkW, const float* __restrict__ mkb,
                 const float* __restrict__ mkg, const float* __restrict__ mkbe,
                 float* __restrict__ rfk, float* __restrict__ beta)
{
    const int blk = blockIdx.x;
    const int c  = blk & 31;
    const int bh = blk >> 5;
    const int h  = bh % Hx;
    const int b  = bh / Hx;
    const int d  = threadIdx.x;

    __shared__ float qm[64], km[64], k0s[64], k1s[64], v0s[64], v1s[64];
    __shared__ float red[2];
    __shared__ float probs[2];

    qm[d] = qmean[((long long)bh * 32 + c) * 64 + d];
    {
        const float* kb = k + ((long long)(b * Kx + c * 2)) * Cx + h * DHx + d;
        const float k0v = kb[0], k1v = kb[Cx];
        k0s[d] = k0v; k1s[d] = k1v;
        km[d]  = 0.5f * (k0v + k1v);
        const float* vb = v + ((long long)(b * Kx + c * 2)) * Cx + h * DHx + d;
        v0s[d] = vb[0]; v1s[d] = vb[Cx];
    }
    __syncthreads();

    float yq = mqb[d], yk = mkb[d];
    #pragma unroll 8
    for (int e = 0; e < 64; e++) {
        yq = fmaf(qm[e], mqW[e * 64 + d], yq);
        yk = fmaf(km[e], mkW[e * 64 + d], yk);
    }

    float m  = blk_reduce64(yq, red) * (1.f / 64.f);
    float dv = yq - m;
    float var = blk_reduce64(dv * dv, red) * (1.f / 64.f);
    const float qbar = dv * rsqrtf(var + LN_EPSx) * mqg[d] + mqbe[d];

    m  = blk_reduce64(yk, red) * (1.f / 64.f);
    dv = yk - m;
    var = blk_reduce64(dv * dv, red) * (1.f / 64.f);
    const float kbar = dv * rsqrtf(var + LN_EPSx) * mkg[d] + mkbe[d];

    rfk[((long long)bh * 32 + c) * 64 + d] = kbar;

    const float mu = 0.5f * (qbar + kbar);

    const float s0 = blk_reduce64(mu * k0s[d], red);
    const float n0 = blk_reduce64(k0s[d] * k0s[d], red);
    const float s1 = blk_reduce64(mu * k1s[d], red);
    const float n1 = blk_reduce64(k1s[d] * k1s[d], red);

    if (d == 0) {
        const float dn = 0.125f;
        const float l0 = dn * s0 - 0.5f * dn * n0;
        const float l1 = dn * s1 - 0.5f * dn * n1;
        const float mx = fmaxf(l0, l1);
        const float e0 = expf(l0 - mx);
        const float e1 = expf(l1 - mx);
        const float inv = 1.f / (e0 + e1);
        probs[0] = e0 * inv;
        probs[1] = e1 * inv;
    }
    __syncthreads();

    beta[((long long)bh * 32 + c) * 64 + d] = probs[0] * v0s[d] + probs[1] * v1s[d];
}

// ------------------------- attention (fp16 q in, fp16 out) -------------------------
__global__ __launch_bounds__(256)
void attn_kernel(const __half* __restrict__ qh, const float* __restrict__ k,
                 const float* __restrict__ v,
                 const float* __restrict__ rfk, const float* __restrict__ betag,
                 __half* __restrict__ outH)
{
    const int blk = blockIdx.x;
    const int w  = blk & 31;
    const int bh = blk >> 5;
    const int h  = bh % Hx;
    const int b  = bh / Hx;

    __shared__ float qs [32][65];
    __shared__ float kbs[32][64];
    __shared__ float bes[32][64];
    __shared__ float wks[2][64];
    __shared__ float wvs[2][64];
    __shared__ float lg [32][35];

    const int t = threadIdx.x;

    for (int idx = t; idx < 2048; idx += 256) {
        const int i = idx >> 6, d = idx & 63;
        qs [i][d] = __half2float(qh[((long long)(b * Nx + w * 32 + i)) * Cx + h * DHx + d]);
        kbs[i][d] = rfk  [((long long)bh * 32 + i) * 64 + d];
        bes[i][d] = betag[((long long)bh * 32 + i) * 64 + d];
    }
    if (t < 128) {
        const int j = t >> 6, d = t & 63;
        wks[j][d] = k[((long long)(b * Kx + w * 2 + j)) * Cx + h * DHx + d];
        wvs[j][d] = v[((long long)(b * Kx + w * 2 + j)) * Cx + h * DHx + d];
    }
    __syncthreads();

    {
        const int i   = t & 31;
        const int sl0 = t >> 5;
        for (int slot = sl0; slot < 34; slot += 8) {
            const float* kv = (slot < 2) ? &wks[slot][0] : &kbs[slot - 2][0];
            float s = 0.f;
            #pragma unroll
            for (int e = 0; e < 64; e++) s = fmaf(qs[i][e], kv[e], s);
            lg[i][slot] = s * SCALEx;
        }
    }
    __syncthreads();

    if (t < 32) {
        float mx = -1e30f;
        #pragma unroll
        for (int s = 0; s < 34; s++) mx = fmaxf(mx, lg[t][s]);
        float sum = 0.f;
        #pragma unroll
        for (int s = 0; s < 34; s++) { const float e = expf(lg[t][s] - mx); lg[t][s] = e; sum += e; }
        const float inv = 1.f / sum;
        #pragma unroll
        for (int s = 0; s < 34; s++) lg[t][s] *= inv;
    }
    __syncthreads();

    const int d = t & 63;
    #pragma unroll
    for (int p = 0; p < 8; p++) {
        const int ii = p * 4 + (t >> 6);
        float acc = lg[ii][0] * wvs[0][d] + lg[ii][1] * wvs[1][d];
        #pragma unroll
        for (int c2 = 0; c2 < 32; c2++)
            acc = fmaf(lg[ii][2 + c2], bes[c2][d], acc);
        const long long ro = ((long long)(b * Nx + w * 32 + ii)) * Cx + h * DHx + d;
        outH[ro] = __float2half(acc);
    }
}

// ------------------------- launch -------------------------
static cudaStream_t g_s1 = nullptr;
static cudaEvent_t  g_evA = nullptr, g_evB = nullptr;

extern "C" void kernel_launch(void* const* d_in, const int* in_sizes, int n_in,
                              void* d_out, int out_size)
{
    const float* query = (const float*)d_in[0];
    const float* key   = (const float*)d_in[1];
    const float* value = (const float*)d_in[2];
    const float* Wq    = (const float*)d_in[3];
    const float* bq    = (const float*)d_in[4];
    const float* Wk    = (const float*)d_in[5];
    const float* bk    = (const float*)d_in[6];
    const float* Wv    = (const float*)d_in[7];
    const float* bv    = (const float*)d_in[8];
    const float* Wo    = (const float*)d_in[9];
    const float* bo    = (const float*)d_in[10];
    const float* kds   = (const float*)d_in[11];
    const float* vds   = (const float*)d_in[12];
    const float* mqW   = (const float*)d_in[13];
    const float* mqb   = (const float*)d_in[14];
    const float* mqg   = (const float*)d_in[15];
    const float* mqbe  = (const float*)d_in[16];
    const float* mkW   = (const float*)d_in[17];
    const float* mkb   = (const float*)d_in[18];
    const float* mkg   = (const float*)d_in[19];
    const float* mkbe  = (const float*)d_in[20];
    float* out = (float*)d_out;

    if (!g_s1) {
        cudaStreamCreateWithFlags(&g_s1, cudaStreamNonBlocking);
        cudaEventCreateWithFlags(&g_evA, cudaEventDisableTiming);
        cudaEventCreateWithFlags(&g_evB, cudaEventDisableTiming);
    }

    float *kk, *vv, *qmean, *rfk, *beta;
    cudaGetSymbolAddress((void**)&kk,    g_k);
    cudaGetSymbolAddress((void**)&vv,    g_v);
    cudaGetSymbolAddress((void**)&qmean, g_qmean);
    cudaGetSymbolAddress((void**)&rfk,   g_rfk);
    cudaGetSymbolAddress((void**)&beta,  g_beta);

    __half *qinH, *qH, *attH, *kdsH, *vdsH;
    __half *keyTH, *valTH, *kdH, *vdH;
    __half *wqTH, *wkTH, *wvTH, *woTH;
    cudaGetSymbolAddress((void**)&qinH,  g_qinH);
    cudaGetSymbolAddress((void**)&qH,    g_qH);
    cudaGetSymbolAddress((void**)&attH,  g_attH);
    cudaGetSymbolAddress((void**)&kdsH,  g_kdsH);
    cudaGetSymbolAddress((void**)&vdsH,  g_vdsH);
    cudaGetSymbolAddress((void**)&keyTH, g_keyTH);
    cudaGetSymbolAddress((void**)&valTH, g_valTH);
    cudaGetSymbolAddress((void**)&kdH,   g_kdH);
    cudaGetSymbolAddress((void**)&vdH,   g_vdH);
    cudaGetSymbolAddress((void**)&wqTH,  g_wqTH);
    cudaGetSymbolAddress((void**)&wkTH,  g_wkTH);
    cudaGetSymbolAddress((void**)&wvTH,  g_wvTH);
    cudaGetSymbolAddress((void**)&woTH,  g_woTH);

    cudaFuncSetAttribute(gemm_mma<0>, cudaFuncAttributeMaxDynamicSharedMemorySize, GSMEM);
    cudaFuncSetAttribute(gemm_mma<2>, cudaFuncAttributeMaxDynamicSharedMemorySize, GSMEM);
    cudaFuncSetAttribute(gemm_mma<3>, cudaFuncAttributeMaxDynamicSharedMemorySize, GSMEM);

    // fork event for graph capture
    cudaEventRecord(g_evA, 0);
    cudaStreamWaitEvent(g_s1, g_evA, 0);

    // ---- main-chain prep ----
    {
        long long t4 = (long long)Bx * Nx * Cx / 4;
        convert16<<<(unsigned)((t4 + 255) / 256), 256>>>(query, qinH, t4);
    }
    transpose16<<<dim3(Cx / 64, Cx / 64, 1), 256>>>(Wq, wqTH, Cx, Cx, 0, 0);
    transpose16<<<dim3(Cx / 64, Cx / 64, 1), 256>>>(Wo, woTH, Cx, Cx, 0, 0);
    {
        long long t4 = (long long)Kx * Nx / 4;
        convert16<<<(unsigned)((t4 + 255) / 256), 256, 0, g_s1>>>(kds, kdsH, t4);
        convert16<<<(unsigned)((t4 + 255) / 256), 256, 0, g_s1>>>(vds, vdsH, t4);
    }

    // ---- q = query @ Wq + bq -> fp16 q (with bias) + per-chunk means ----
    gemm_mma<3><<<dim3(Cx / 128, (Bx * Nx) / 128, 1), 256, GSMEM>>>(
        qinH, wqTH, bq, qmean, qH,
        Bx * Nx, Cx, Cx, 0, 0, 0);

    // ---- side stream: KV chain ----
    transpose16<<<dim3(Cx / 64, Cx / 64, 1), 256, 0, g_s1>>>(Wk, wkTH, Cx, Cx, 0, 0);
    transpose16<<<dim3(Cx / 64, Cx / 64, 1), 256, 0, g_s1>>>(Wv, wvTH, Cx, Cx, 0, 0);
    transpose16<<<dim3(Cx / 64, Nx / 64, Bx), 256, 0, g_s1>>>(key, keyTH, Nx, Cx,
        (long long)Nx * Cx, (long long)Cx * Nx);
    transpose16<<<dim3(Cx / 64, Nx / 64, Bx), 256, 0, g_s1>>>(value, valTH, Nx, Cx,
        (long long)Nx * Cx, (long long)Cx * Nx);
    gemm_mma<2><<<dim3(Cx / 128, 1, Bx), 256, GSMEM, g_s1>>>(
        kdsH, keyTH, nullptr, nullptr, kdH,
        Kx, Cx, Nx, 0, (long long)Cx * Nx, (long long)Kx * Cx);
    gemm_mma<2><<<dim3(Cx / 128, 1, Bx), 256, GSMEM, g_s1>>>(
        vdsH, valTH, nullptr, nullptr, vdH,
        Kx, Cx, Nx, 0, (long long)Cx * Nx, (long long)Kx * Cx);
    gemm_mma<0><<<dim3(Cx / 128, (Bx * Kx) / 128, 1), 256, GSMEM, g_s1>>>(
        kdH, wkTH, bk, kk, nullptr,
        Bx * Kx, Cx, Cx, 0, 0, 0);
    gemm_mma<0><<<dim3(Cx / 128, (Bx * Kx) / 128, 1), 256, GSMEM, g_s1>>>(
        vdH, wvTH, bv, vv, nullptr,
        Bx * Kx, Cx, Cx, 0, 0, 0);
    cudaEventRecord(g_evB, g_s1);

    // ================= join =================
    cudaStreamWaitEvent(0, g_evB, 0);

    // chunk summaries + attention
    chunk_stats<<<Bx * Hx * 32, 64>>>(qmean, kk, vv,
                                      mqW, mqb, mqg, mqbe,
                                      mkW, mkb, mkg, mkbe,
                                      rfk, beta);
    attn_kernel<<<Bx * Hx * 32, 256>>>(qH, kk, vv, rfk, beta, attH);

    // out = att @ Wo + bo (pure fp16)
    gemm_mma<0><<<dim3(Cx / 128, (Bx * Nx) / 128, 1), 256, GSMEM>>>(
        attH, woTH, bo, out, nullptr,
        Bx * Nx, Cx, Cx, 0, 0, 0);
}

// round 15
// speedup vs baseline: 1.5963x; 1.0888x over previous
#include <cuda_runtime.h>
#include <cuda_fp16.h>
#include <math.h>
#include <stdint.h>

// Problem constants
#define Bx   64
#define Nx   1024
#define Cx   768
#define Hx   12
#define DHx  64
#define Kx   64
#define SCALEx 0.125f
#define LN_EPSx 1e-6f

// ------------------------- device scratch -------------------------
__device__ float g_k    [(long long)Bx * Kx * Cx];
__device__ float g_v    [(long long)Bx * Kx * Cx];
__device__ float g_qmean[(long long)Bx * Hx * 32 * DHx];
__device__ float g_rfk  [(long long)Bx * Hx * 32 * DHx];
__device__ float g_beta [(long long)Bx * Hx * 32 * DHx];

// fp16 planes (row-major)
__device__ __half g_qinH [(long long)Bx * Nx * Cx];
__device__ __half g_qH   [(long long)Bx * Nx * Cx];
__device__ __half g_attH [(long long)Bx * Nx * Cx];
__device__ __half g_kdsH [Kx * Nx];
__device__ __half g_vdsH [Kx * Nx];
__device__ __half g_keyTH[(long long)Bx * Cx * Nx];
__device__ __half g_valTH[(long long)Bx * Cx * Nx];
__device__ __half g_kdH  [(long long)Bx * Kx * Cx];
__device__ __half g_vdH  [(long long)Bx * Kx * Cx];
__device__ __half g_wqTH [Cx * Cx];
__device__ __half g_wkTH [Cx * Cx];
__device__ __half g_wvTH [Cx * Cx];
__device__ __half g_woTH [Cx * Cx];

// ------------------------- helpers -------------------------
__device__ __forceinline__ uint32_t smem_u32(const void* p) {
    uint32_t a;
    asm("{ .reg .u64 t; cvta.to.shared.u64 t, %1; cvt.u32.u64 %0, t; }" : "=r"(a) : "l"(p));
    return a;
}
__device__ __forceinline__ void cp16(uint32_t dst, const void* src, int srcsz) {
    asm volatile("cp.async.cg.shared.global [%0], [%1], 16, %2;"
                 :: "r"(dst), "l"(src), "r"(srcsz) : "memory");
}
#define CP_COMMIT() asm volatile("cp.async.commit_group;" ::: "memory")
#define CP_WAIT0()  asm volatile("cp.async.wait_group 0;" ::: "memory")

__device__ __forceinline__ void ldm_x4(uint32_t* r, uint32_t a) {
    asm volatile("ldmatrix.sync.aligned.m8n8.x4.shared.b16 {%0,%1,%2,%3}, [%4];"
                 : "=r"(r[0]), "=r"(r[1]), "=r"(r[2]), "=r"(r[3]) : "r"(a));
}
__device__ __forceinline__ void mma_f16(float* d, const uint32_t* a, const uint32_t* b) {
    asm volatile("mma.sync.aligned.m16n8k16.row.col.f32.f16.f16.f32 "
                 "{%0,%1,%2,%3},{%4,%5,%6,%7},{%8,%9},{%0,%1,%2,%3};"
                 : "+f"(d[0]), "+f"(d[1]), "+f"(d[2]), "+f"(d[3])
                 : "r"(a[0]), "r"(a[1]), "r"(a[2]), "r"(a[3]), "r"(b[0]), "r"(b[1]));
}

// ------------------------- convert (row-major, hi only) -------------------------
__global__ __launch_bounds__(256)
void convert16(const float* __restrict__ in,
               __half* __restrict__ oh,
               long long total4)
{
    const long long g = (long long)blockIdx.x * 256 + threadIdx.x;
    if (g >= total4) return;
    float4 f = ((const float4*)in)[g];
    __half h[4];
    h[0] = __float2half(f.x); h[1] = __float2half(f.y);
    h[2] = __float2half(f.z); h[3] = __float2half(f.w);
    *(uint2*)(oh + g * 4) = *(uint2*)h;
}

// ------------------------- transpose (hi plane only) ------------
__global__ __launch_bounds__(256)
void transpose16(const float* __restrict__ in,
                 __half* __restrict__ oh,
                 int R, int Cc, long long sIn, long long sOut)
{
    __shared__ float t[64][65];
    in += (long long)blockIdx.z * sIn;
    oh += (long long)blockIdx.z * sOut;
    const int r0 = blockIdx.y * 64;
    const int c0 = blockIdx.x * 64;
    const int tid = threadIdx.x;
    #pragma unroll
    for (int it = 0; it < 4; it++) {
        const int idx = it * 256 + tid;
        const int row = idx >> 4;
        const int c4  = (idx & 15) * 4;
        float4 f = *(const float4*)(in + (long long)(r0 + row) * Cc + c0 + c4);
        t[row][c4 + 0] = f.x; t[row][c4 + 1] = f.y;
        t[row][c4 + 2] = f.z; t[row][c4 + 3] = f.w;
    }
    __syncthreads();
    #pragma unroll
    for (int it = 0; it < 2; it++) {
        const int idx = it * 256 + tid;
        const int oc = idx >> 3;
        const int k8 = (idx & 7) * 8;
        __half h[8];
        #pragma unroll
        for (int j = 0; j < 8; j++)
            h[j] = __float2half(t[k8 + j][oc]);
        const long long base = (long long)(c0 + oc) * R + r0 + k8;
        *(uint4*)(oh + base) = *(uint4*)h;
    }
}

// ------------------------- mma.sync GEMM (fp16, ldmatrix, 64-k chunks) -----------
// MODE 0: fp32 out (+bias)
// MODE 2: fp16 out (no bias)
// MODE 3: fp16 out (+bias) AND per-32-row column means (+bias) into Cf
#define TSB2 144
#define MATB (128 * TSB2)          // 18432 bytes per matrix tile
#define BUF2 (2 * MATB)            // 36864 bytes per buffer (A + B)
#define GSMEM (2 * BUF2)           // 73728

template<int MODE>
__global__ __launch_bounds__(256)
void gemm_mma(const __half* __restrict__ Ah,
              const __half* __restrict__ Bh,
              const float* __restrict__ bias,
              float* __restrict__ Cf,
              __half* __restrict__ Ch,
              int M, int Nn, int Kk,
              long long sA, long long sB, long long sC)
{
    extern __shared__ char sm[];
    const long long z = blockIdx.z;
    Ah += z * sA;
    Bh += z * sB;

    const int bRow = blockIdx.y * 128;
    const int bCol = blockIdx.x * 128;
    const int tid  = threadIdx.x;
    const int lane = tid & 31;
    const int wid  = tid >> 5;
    const int warpRow = (wid & 3) * 32;
    const int warpCol = (wid >> 2) * 64;
    const uint32_t sb = smem_u32(sm);

    float acc[2][8][4];
    #pragma unroll
    for (int i = 0; i < 2; i++)
        #pragma unroll
        for (int j = 0; j < 8; j++)
            #pragma unroll
            for (int r = 0; r < 4; r++) acc[i][j][r] = 0.f;

    const int nCh = Kk / 64;

    auto loadChunk = [&](int c, int buf) {
        const int k0 = c * 64;
        const uint32_t d = sb + buf * BUF2;
        #pragma unroll
        for (int it = 0; it < 4; it++) {
            const int idx = it * 256 + tid;
            const int row = idx >> 3;
            const int seg = idx & 7;
            const uint32_t doff = row * TSB2 + seg * 16;
            const int ar = bRow + row;
            const int sz = (ar < M) ? 16 : 0;
            const long long aoff = (long long)((ar < M) ? ar : 0) * Kk + k0 + seg * 8;
            cp16(d + doff, Ah + aoff, sz);
            const long long boff = (long long)(bCol + row) * Kk + k0 + seg * 8;
            cp16(d + MATB + doff, Bh + boff, 16);
        }
        CP_COMMIT();
    };

    const int aRowSel = (lane & 15);
    const int aKHalf  = (lane >> 4) & 1;
    const int bRowSel = (lane & 7) + ((lane >> 4) & 1) * 8;
    const int bKHalf  = (lane >> 3) & 1;

    loadChunk(0, 0);
    for (int c = 0; c < nCh; c++) {
        const int buf = c & 1;
        CP_WAIT0();          // chunk c (issued last iteration) complete
        __syncthreads();     // publish chunk c; certifies compute(c-1) done
        if (c + 1 < nCh) loadChunk(c + 1, buf ^ 1);  // overwrite c-1's buffer (safe)

        const uint32_t aT = sb + buf * BUF2;
        const uint32_t bT = aT + MATB;

        #pragma unroll
        for (int s = 0; s < 4; s++) {
            const int kb = s * 32;
            uint32_t ah[2][4];
            #pragma unroll
            for (int i = 0; i < 2; i++) {
                const uint32_t ad = aT + (warpRow + i * 16 + aRowSel) * TSB2
                                       + kb + aKHalf * 16;
                ldm_x4(ah[i], ad);
            }
            #pragma unroll
            for (int jp = 0; jp < 4; jp++) {
                const uint32_t bd = bT + (warpCol + jp * 16 + bRowSel) * TSB2
                                       + kb + bKHalf * 16;
                uint32_t bh[4];
                ldm_x4(bh, bd);
                #pragma unroll
                for (int jj = 0; jj < 2; jj++) {
                    #pragma unroll
                    for (int i = 0; i < 2; i++) {
                        mma_f16(acc[i][2 * jp + jj], ah[i], &bh[2 * jj]);
                    }
                }
            }
        }
    }

    // ------------- epilogue -------------
    const int rB = bRow + warpRow + (lane >> 2);
    if (MODE == 0) {
        float* C = Cf + z * sC;
        #pragma unroll
        for (int i = 0; i < 2; i++) {
            #pragma unroll
            for (int j = 0; j < 8; j++) {
                const int col = bCol + warpCol + j * 8 + (lane & 3) * 2;
                float bx = 0.f, by = 0.f;
                if (bias) { bx = bias[col]; by = bias[col + 1]; }
                const int r = rB + i * 16;
                if (r < M) {
                    float2 o = make_float2(acc[i][j][0] + bx, acc[i][j][1] + by);
                    *(float2*)(C + (long long)r * Nn + col) = o;
                }
                if (r + 8 < M) {
                    float2 o = make_float2(acc[i][j][2] + bx, acc[i][j][3] + by);
                    *(float2*)(C + (long long)(r + 8) * Nn + col) = o;
                }
            }
        }
    } else if (MODE == 2) {
        __half* CH = Ch + z * sC;
        #pragma unroll
        for (int i = 0; i < 2; i++) {
            #pragma unroll
            for (int j = 0; j < 8; j++) {
                const int col = bCol + warpCol + j * 8 + (lane & 3) * 2;
                #pragma unroll
                for (int half = 0; half < 2; half++) {
                    const int r = rB + i * 16 + half * 8;
                    if (r >= M) continue;
                    __half hp[2];
                    hp[0] = __float2half(acc[i][j][2 * half + 0]);
                    hp[1] = __float2half(acc[i][j][2 * half + 1]);
                    *(uint32_t*)(CH + (long long)r * Nn + col) = *(uint32_t*)hp;
                }
            }
        }
    } else {  // MODE == 3: fp16 (+bias) out + column means into Cf (qmean)
        __half* CH = Ch;
        #pragma unroll
        for (int i = 0; i < 2; i++) {
            #pragma unroll
            for (int j = 0; j < 8; j++) {
                const int col = bCol + warpCol + j * 8 + (lane & 3) * 2;
                const float bx = bias[col], by = bias[col + 1];
                #pragma unroll
                for (int half = 0; half < 2; half++) {
                    const int r = rB + i * 16 + half * 8;
                    __half hp[2];
                    hp[0] = __float2half(acc[i][j][2 * half + 0] + bx);
                    hp[1] = __float2half(acc[i][j][2 * half + 1] + by);
                    *(uint32_t*)(CH + (long long)r * Nn + col) = *(uint32_t*)hp;
                }
            }
        }
        const int rowBase = bRow + warpRow;
        const int b = rowBase >> 10;
        const int c = (rowBase >> 5) & 31;
        #pragma unroll
        for (int j = 0; j < 8; j++) {
            float s0 = acc[0][j][0] + acc[0][j][2] + acc[1][j][0] + acc[1][j][2];
            float s1 = acc[0][j][1] + acc[0][j][3] + acc[1][j][1] + acc[1][j][3];
            #pragma unroll
            for (int o = 16; o >= 4; o >>= 1) {
                s0 += __shfl_down_sync(0xffffffffu, s0, o);
                s1 += __shfl_down_sync(0xffffffffu, s1, o);
            }
            if ((lane >> 2) == 0) {
                const int col = bCol + warpCol + j * 8 + lane * 2;
                const int h = col >> 6, d = col & 63;
                float* qm = Cf + (((long long)(b * Hx + h)) * 32 + c) * 64 + d;
                qm[0] = s0 * (1.f / 32.f) + bias[col];
                qm[1] = s1 * (1.f / 32.f) + bias[col + 1];
            }
        }
    }
}

// ------------------------- chunk stats -------------------------
__device__ __forceinline__ float blk_reduce64(float x, float* red)
{
    const int d = threadIdx.x;
    #pragma unroll
    for (int o = 16; o > 0; o >>= 1)
        x += __shfl_down_sync(0xffffffffu, x, o);
    if ((d & 31) == 0) red[d >> 5] = x;
    __syncthreads();
    const float r = red[0] + red[1];
    __syncthreads();
    return r;
}

__global__ __launch_bounds__(64)
void chunk_stats(const float* __restrict__ qmean, const float* __restrict__ k,
                 const float* __restrict__ v,
                 const float* __restrict__ mqW, const float* __restrict__ mqb,
                 const float* __restrict__ mqg, const float* __restrict__ mqbe,
                 const float* __restrict__ mkW, const float* __restrict__ mkb,
                 const float* __restrict__ mkg, const float* __restrict__ mkbe,
                 float* __restrict__ rfk, float* __restrict__ beta)
{
    const int blk = blockIdx.x;
    const int c  = blk & 31;
    const int bh = blk >> 5;
    const int h  = bh % Hx;
    const int b  = bh / Hx;
    const int d  = threadIdx.x;

    __shared__ float qm[64], km[64], k0s[64], k1s[64], v0s[64], v1s[64];
    __shared__ float red[2];
    __shared__ float probs[2];

    qm[d] = qmean[((long long)bh * 32 + c) * 64 + d];
    {
        const float* kb = k + ((long long)(b * Kx + c * 2)) * Cx + h * DHx + d;
        const float k0v = kb[0], k1v = kb[Cx];
        k0s[d] = k0v; k1s[d] = k1v;
        km[d]  = 0.5f * (k0v + k1v);
        const float* vb = v + ((long long)(b * Kx + c * 2)) * Cx + h * DHx + d;
        v0s[d] = vb[0]; v1s[d] = vb[Cx];
    }
    __syncthreads();

    float yq = mqb[d], yk = mkb[d];
    #pragma unroll 8
    for (int e = 0; e < 64; e++) {
        yq = fmaf(qm[e], mqW[e * 64 + d], yq);
        yk = fmaf(km[e], mkW[e * 64 + d], yk);
    }

    float m  = blk_reduce64(yq, red) * (1.f / 64.f);
    float dv = yq - m;
    float var = blk_reduce64(dv * dv, red) * (1.f / 64.f);
    const float qbar = dv * rsqrtf(var + LN_EPSx) * mqg[d] + mqbe[d];

    m  = blk_reduce64(yk, red) * (1.f / 64.f);
    dv = yk - m;
    var = blk_reduce64(dv * dv, red) * (1.f / 64.f);
    const float kbar = dv * rsqrtf(var + LN_EPSx) * mkg[d] + mkbe[d];

    rfk[((long long)bh * 32 + c) * 64 + d] = kbar;

    const float mu = 0.5f * (qbar + kbar);

    const float s0 = blk_reduce64(mu * k0s[d], red);
    const float n0 = blk_reduce64(k0s[d] * k0s[d], red);
    const float s1 = blk_reduce64(mu * k1s[d], red);
    const float n1 = blk_reduce64(k1s[d] * k1s[d], red);

    if (d == 0) {
        const float dn = 0.125f;
        const float l0 = dn * s0 - 0.5f * dn * n0;
        const float l1 = dn * s1 - 0.5f * dn * n1;
        const float mx = fmaxf(l0, l1);
        const float e0 = expf(l0 - mx);
        const float e1 = expf(l1 - mx);
        const float inv = 1.f / (e0 + e1);
        probs[0] = e0 * inv;
        probs[1] = e1 * inv;
    }
    __syncthreads();

    beta[((long long)bh * 32 + c) * 64 + d] = probs[0] * v0s[d] + probs[1] * v1s[d];
}

// ------------------------- attention (fp16 q in, fp16 out) -------------------------
__global__ __launch_bounds__(256)
void attn_kernel(const __half* __restrict__ qh, const float* __restrict__ k,
                 const float* __restrict__ v,
                 const float* __restrict__ rfk, const float* __restrict__ betag,
                 __half* __restrict__ outH)
{
    const int blk = blockIdx.x;
    const int w  = blk & 31;
    const int bh = blk >> 5;
    const int h  = bh % Hx;
    const int b  = bh / Hx;

    __shared__ float qs [32][65];
    __shared__ float kbs[32][64];
    __shared__ float bes[32][64];
    __shared__ float wks[2][64];
    __shared__ float wvs[2][64];
    __shared__ float lg [32][35];

    const int t = threadIdx.x;

    for (int idx = t; idx < 2048; idx += 256) {
        const int i = idx >> 6, d = idx & 63;
        qs [i][d] = __half2float(qh[((long long)(b * Nx + w * 32 + i)) * Cx + h * DHx + d]);
        kbs[i][d] = rfk  [((long long)bh * 32 + i) * 64 + d];
        bes[i][d] = betag[((long long)bh * 32 + i) * 64 + d];
    }
    if (t < 128) {
        const int j = t >> 6, d = t & 63;
        wks[j][d] = k[((long long)(b * Kx + w * 2 + j)) * Cx + h * DHx + d];
        wvs[j][d] = v[((long long)(b * Kx + w * 2 + j)) * Cx + h * DHx + d];
    }
    __syncthreads();

    {
        const int i   = t & 31;
        const int sl0 = t >> 5;
        for (int slot = sl0; slot < 34; slot += 8) {
            const float* kv = (slot < 2) ? &wks[slot][0] : &kbs[slot - 2][0];
            float s = 0.f;
            #pragma unroll
            for (int e = 0; e < 64; e++) s = fmaf(qs[i][e], kv[e], s);
            lg[i][slot] = s * SCALEx;
        }
    }
    __syncthreads();

    if (t < 32) {
        float mx = -1e30f;
        #pragma unroll
        for (int s = 0; s < 34; s++) mx = fmaxf(mx, lg[t][s]);
        float sum = 0.f;
        #pragma unroll
        for (int s = 0; s < 34; s++) { const float e = expf(lg[t][s] - mx); lg[t][s] = e; sum += e; }
        const float inv = 1.f / sum;
        #pragma unroll
        for (int s = 0; s < 34; s++) lg[t][s] *= inv;
    }
    __syncthreads();

    const int d = t & 63;
    #pragma unroll
    for (int p = 0; p < 8; p++) {
        const int ii = p * 4 + (t >> 6);
        float acc = lg[ii][0] * wvs[0][d] + lg[ii][1] * wvs[1][d];
        #pragma unroll
        for (int c2 = 0; c2 < 32; c2++)
            acc = fmaf(lg[ii][2 + c2], bes[c2][d], acc);
        const long long ro = ((long long)(b * Nx + w * 32 + ii)) * Cx + h * DHx + d;
        outH[ro] = __float2half(acc);
    }
}

// ------------------------- launch -------------------------
static cudaStream_t g_s1 = nullptr;
static cudaEvent_t  g_evA = nullptr, g_evB = nullptr;

extern "C" void kernel_launch(void* const* d_in, const int* in_sizes, int n_in,
                              void* d_out, int out_size)
{
    const float* query = (const float*)d_in[0];
    const float* key   = (const float*)d_in[1];
    const float* value = (const float*)d_in[2];
    const float* Wq    = (const float*)d_in[3];
    const float* bq    = (const float*)d_in[4];
    const float* Wk    = (const float*)d_in[5];
    const float* bk    = (const float*)d_in[6];
    const float* Wv    = (const float*)d_in[7];
    const float* bv    = (const float*)d_in[8];
    const float* Wo    = (const float*)d_in[9];
    const float* bo    = (const float*)d_in[10];
    const float* kds   = (const float*)d_in[11];
    const float* vds   = (const float*)d_in[12];
    const float* mqW   = (const float*)d_in[13];
    const float* mqb   = (const float*)d_in[14];
    const float* mqg   = (const float*)d_in[15];
    const float* mqbe  = (const float*)d_in[16];
    const float* mkW   = (const float*)d_in[17];
    const float* mkb   = (const float*)d_in[18];
    const float* mkg   = (const float*)d_in[19];
    const float* mkbe  = (const float*)d_in[20];
    float* out = (float*)d_out;

    if (!g_s1) {
        cudaStreamCreateWithFlags(&g_s1, cudaStreamNonBlocking);
        cudaEventCreateWithFlags(&g_evA, cudaEventDisableTiming);
        cudaEventCreateWithFlags(&g_evB, cudaEventDisableTiming);
    }

    float *kk, *vv, *qmean, *rfk, *beta;
    cudaGetSymbolAddress((void**)&kk,    g_k);
    cudaGetSymbolAddress((void**)&vv,    g_v);
    cudaGetSymbolAddress((void**)&qmean, g_qmean);
    cudaGetSymbolAddress((void**)&rfk,   g_rfk);
    cudaGetSymbolAddress((void**)&beta,  g_beta);

    __half *qinH, *qH, *attH, *kdsH, *vdsH;
    __half *keyTH, *valTH, *kdH, *vdH;
    __half *wqTH, *wkTH, *wvTH, *woTH;
    cudaGetSymbolAddress((void**)&qinH,  g_qinH);
    cudaGetSymbolAddress((void**)&qH,    g_qH);
    cudaGetSymbolAddress((void**)&attH,  g_attH);
    cudaGetSymbolAddress((void**)&kdsH,  g_kdsH);
    cudaGetSymbolAddress((void**)&vdsH,  g_vdsH);
    cudaGetSymbolAddress((void**)&keyTH, g_keyTH);
    cudaGetSymbolAddress((void**)&valTH, g_valTH);
    cudaGetSymbolAddress((void**)&kdH,   g_kdH);
    cudaGetSymbolAddress((void**)&vdH,   g_vdH);
    cudaGetSymbolAddress((void**)&wqTH,  g_wqTH);
    cudaGetSymbolAddress((void**)&wkTH,  g_wkTH);
    cudaGetSymbolAddress((void**)&wvTH,  g_wvTH);
    cudaGetSymbolAddress((void**)&woTH,  g_woTH);

    cudaFuncSetAttribute(gemm_mma<0>, cudaFuncAttributeMaxDynamicSharedMemorySize, GSMEM);
    cudaFuncSetAttribute(gemm_mma<2>, cudaFuncAttributeMaxDynamicSharedMemorySize, GSMEM);
    cudaFuncSetAttribute(gemm_mma<3>, cudaFuncAttributeMaxDynamicSharedMemorySize, GSMEM);

    // fork event for graph capture
    cudaEventRecord(g_evA, 0);
    cudaStreamWaitEvent(g_s1, g_evA, 0);

    // ---- main-chain prep ----
    {
        long long t4 = (long long)Bx * Nx * Cx / 4;
        convert16<<<(unsigned)((t4 + 255) / 256), 256>>>(query, qinH, t4);
    }
    transpose16<<<dim3(Cx / 64, Cx / 64, 1), 256>>>(Wq, wqTH, Cx, Cx, 0, 0);
    transpose16<<<dim3(Cx / 64, Cx / 64, 1), 256>>>(Wo, woTH, Cx, Cx, 0, 0);
    {
        long long t4 = (long long)Kx * Nx / 4;
        convert16<<<(unsigned)((t4 + 255) / 256), 256, 0, g_s1>>>(kds, kdsH, t4);
        convert16<<<(unsigned)((t4 + 255) / 256), 256, 0, g_s1>>>(vds, vdsH, t4);
    }

    // ---- q = query @ Wq + bq -> fp16 q (with bias) + per-chunk means ----
    gemm_mma<3><<<dim3(Cx / 128, (Bx * Nx) / 128, 1), 256, GSMEM>>>(
        qinH, wqTH, bq, qmean, qH,
        Bx * Nx, Cx, Cx, 0, 0, 0);

    // ---- side stream: KV chain ----
    transpose16<<<dim3(Cx / 64, Cx / 64, 1), 256, 0, g_s1>>>(Wk, wkTH, Cx, Cx, 0, 0);
    transpose16<<<dim3(Cx / 64, Cx / 64, 1), 256, 0, g_s1>>>(Wv, wvTH, Cx, Cx, 0, 0);
    transpose16<<<dim3(Cx / 64, Nx / 64, Bx), 256, 0, g_s1>>>(key, keyTH, Nx, Cx,
        (long long)Nx * Cx, (long long)Cx * Nx);
    transpose16<<<dim3(Cx / 64, Nx / 64, Bx), 256, 0, g_s1>>>(value, valTH, Nx, Cx,
        (long long)Nx * Cx, (long long)Cx * Nx);
    gemm_mma<2><<<dim3(Cx / 128, 1, Bx), 256, GSMEM, g_s1>>>(
        kdsH, keyTH, nullptr, nullptr, kdH,
        Kx, Cx, Nx, 0, (long long)Cx * Nx, (long long)Kx * Cx);
    gemm_mma<2><<<dim3(Cx / 128, 1, Bx), 256, GSMEM, g_s1>>>(
        vdsH, valTH, nullptr, nullptr, vdH,
        Kx, Cx, Nx, 0, (long long)Cx * Nx, (long long)Kx * Cx);
    gemm_mma<0><<<dim3(Cx / 128, (Bx * Kx) / 128, 1), 256, GSMEM, g_s1>>>(
        kdH, wkTH, bk, kk, nullptr,
        Bx * Kx, Cx, Cx, 0, 0, 0);
    gemm_mma<0><<<dim3(Cx / 128, (Bx * Kx) / 128, 1), 256, GSMEM, g_s1>>>(
        vdH, wvTH, bv, vv, nullptr,
        Bx * Kx, Cx, Cx, 0, 0, 0);
    cudaEventRecord(g_evB, g_s1);

    // ================= join =================
    cudaStreamWaitEvent(0, g_evB, 0);

    // chunk summaries + attention
    chunk_stats<<<Bx * Hx * 32, 64>>>(qmean, kk, vv,
                                      mqW, mqb, mqg, mqbe,
                                      mkW, mkb, mkg, mkbe,
                                      rfk, beta);
    attn_kernel<<<Bx * Hx * 32, 256>>>(qH, kk, vv, rfk, beta, attH);

    // out = att @ Wo + bo (pure fp16)
    gemm_mma<0><<<dim3(Cx / 128, (Bx * Nx) / 128, 1), 256, GSMEM>>>(
        attH, woTH, bo, out, nullptr,
        Bx * Nx, Cx, Cx, 0, 0, 0);
}